// round 14
// baseline (speedup 1.0000x reference)
#include <cuda_runtime.h>
#include <cuda_bf16.h>
#include <math.h>
#include <stdint.h>

#define BB 8192
#define TT 128
#define HD 128
#define GG 384
#define NSTEPS 30

typedef unsigned long long ull;

// ---------------- device scratch (static; no allocations allowed) ----------------
__device__ __nv_bfloat16 g_XSb[(size_t)TT * BB * HD];     // 256 MB; reused as fp32 inc later
__device__ __nv_bfloat16 g_hstateb[(size_t)BB * HD];      // encoder final state (bf16)
__device__ uint32_t g_hallb[(size_t)NSTEPS * BB * 64];    // decoder h per step (bf16x2)
__device__ float g_present[(size_t)BB * 6];
__device__ uint32_t g_wencih[24576];                      // ldsm-ready B fragment tiles
__device__ uint32_t g_wenchh[24576];
__device__ uint32_t g_wdecih[24576];
__device__ uint32_t g_wdechh[24576];
__device__ uint32_t g_fc1tb[16384];
__device__ uint32_t g_fc2tb[8192];

// ---------------- helpers ----------------
__device__ __forceinline__ uint32_t packbf(float x, float y) {
    __nv_bfloat162 v = __floats2bfloat162_rn(x, y);
    return *reinterpret_cast<uint32_t*>(&v);
}
__device__ __forceinline__ void mma16(float* d, const unsigned* a, unsigned b0, unsigned b1) {
    asm volatile(
        "mma.sync.aligned.m16n8k16.row.col.f32.bf16.bf16.f32 "
        "{%0,%1,%2,%3}, {%4,%5,%6,%7}, {%8,%9}, {%0,%1,%2,%3};"
        : "+f"(d[0]), "+f"(d[1]), "+f"(d[2]), "+f"(d[3])
        : "r"(a[0]), "r"(a[1]), "r"(a[2]), "r"(a[3]), "r"(b0), "r"(b1));
}
__device__ __forceinline__ unsigned s2u(const void* p) {
    return (unsigned)__cvta_generic_to_shared(p);
}
__device__ __forceinline__ void ldsm4(unsigned a[4], unsigned saddr) {
    asm volatile("ldmatrix.sync.aligned.m8n8.x4.shared.b16 {%0,%1,%2,%3}, [%4];"
                 : "=r"(a[0]), "=r"(a[1]), "=r"(a[2]), "=r"(a[3]) : "r"(saddr));
}
__device__ __forceinline__ float sigm(float x) {
    float t; asm("tanh.approx.f32 %0, %1;" : "=f"(t) : "f"(x * 0.5f));
    return fmaf(t, 0.5f, 0.5f);
}
__device__ __forceinline__ float tanha(float x) {
    float t; asm("tanh.approx.f32 %0, %1;" : "=f"(t) : "f"(x));
    return t;
}
__device__ __forceinline__ float2 ld2(const float* p) { return *reinterpret_cast<const float2*>(p); }
__device__ __forceinline__ void barg(int grp) {
    asm volatile("bar.sync %0, 256;" :: "r"(grp + 1) : "memory");
}
__device__ __forceinline__ void nsleep(unsigned ns) {
    asm volatile("nanosleep.u32 %0;" :: "r"(ns));
}

// cp.async
__device__ __forceinline__ void cpa16(void* smem, const void* g) {
    unsigned saddr = s2u(smem);
    asm volatile("cp.async.cg.shared.global [%0], [%1], 16;" :: "r"(saddr), "l"(g));
}
__device__ __forceinline__ void cp_commit() { asm volatile("cp.async.commit_group;"); }
template <int N> __device__ __forceinline__ void cp_wait() {
    asm volatile("cp.async.wait_group %0;" :: "n"(N));
}

// per-lane byte offset inside a 512B B-tile-pair block for ldsm.x4
__device__ __forceinline__ unsigned bpl(int lane) {
    return ((unsigned)(lane >> 3) << 7) | ((unsigned)(lane & 7) << 4);
}

// ---------------- merged prep + conv (one launch; blocks 0..479 prep, rest conv) ----
__global__ void prep_conv(const float* __restrict__ ewih, const float* __restrict__ ewhh,
                          const float* __restrict__ dwih, const float* __restrict__ dwhh,
                          const float* __restrict__ f1w, const float* __restrict__ f2w,
                          const float* __restrict__ past, const float* __restrict__ cw,
                          const float* __restrict__ cb, const float* __restrict__ bng,
                          const float* __restrict__ bnb, const float* __restrict__ bnm,
                          const float* __restrict__ bnv, float* __restrict__ present) {
    int tid = threadIdx.x;
    if (blockIdx.x < 480) {
        int b = blockIdx.x;
        if (b < 384) {
            int wsel = b / 96;
            const float* src = (wsel == 0) ? ewih : (wsel == 1) ? ewhh : (wsel == 2) ? dwih : dwhh;
            uint32_t* dst = (wsel == 0) ? g_wencih : (wsel == 1) ? g_wenchh
                                                    : (wsel == 2) ? g_wdecih : g_wdechh;
            int e = (b % 96) * 256 + tid;
            int n = e >> 6, k2 = e & 63;
            uint32_t v = packbf(src[n * HD + 2 * k2], src[n * HD + 2 * k2 + 1]);
            int pos = ((k2 >> 2) & 1) * 32 + ((n & 7) << 2) + (k2 & 3);
            dst[((k2 >> 3) * 48 + (n >> 3)) * 64 + pos] = v;
        } else if (b < 448) {
            int e = (b - 384) * 256 + tid;
            int n = e >> 6, k2 = e & 63;
            uint32_t v = packbf(f1w[n * 128 + 2 * k2], f1w[n * 128 + 2 * k2 + 1]);
            int pos = ((k2 >> 2) & 1) * 32 + ((n & 7) << 2) + (k2 & 3);
            g_fc1tb[((k2 >> 3) * 32 + (n >> 3)) * 64 + pos] = v;
        } else {
            int e = (b - 448) * 256 + tid;
            int n = e >> 7, k2 = e & 127;
            uint32_t v = packbf(f2w[n * 256 + 2 * k2], f2w[n * 256 + 2 * k2 + 1]);
            int pos = ((k2 >> 2) & 1) * 32 + ((n & 7) << 2) + (k2 & 3);
            g_fc2tb[((k2 >> 3) * 8 + (n >> 3)) * 64 + pos] = v;
        }
        return;
    }
    // ---- conv part (128 worker threads of 256; all threads hit barriers) ----
    __shared__ float p[6][TT];
    __shared__ __nv_bfloat16 stg[8][HD];
    int b = blockIdx.x - 480, o = tid;
    for (int i = o; i < 6 * TT; i += 256) p[i / TT][i % TT] = past[(size_t)b * 6 * TT + i];
    float w[6][3];
    float bias = 0.0f, scale = 1.0f, shift = 0.0f;
    if (o < HD) {
#pragma unroll
        for (int i = 0; i < 6; i++)
#pragma unroll
            for (int k = 0; k < 3; k++) w[i][k] = cw[(o * 6 + i) * 3 + k];
        bias = cb[o];
        scale = bng[0] * rsqrtf(bnv[0] + 1e-5f);
        shift = bnb[0] - bnm[0] * scale;
    }
    __syncthreads();
    for (int t0 = 0; t0 < TT; t0 += 8) {
        if (o < HD) {
#pragma unroll
            for (int t2 = 0; t2 < 8; t2++) {
                int t = t0 + t2;
                float acc = bias;
#pragma unroll
                for (int i = 0; i < 6; i++) {
                    float l = (t > 0) ? p[i][t - 1] : 0.0f;
                    float r = (t < TT - 1) ? p[i][t + 1] : 0.0f;
                    acc += l * w[i][0] + p[i][t] * w[i][1] + r * w[i][2];
                }
                float v = fmaxf(acc, 0.0f) * scale + shift;
                stg[t2][o] = __float2bfloat16(v);
            }
        }
        __syncthreads();
        if (o < HD) {
            int tl = o >> 4, ch = o & 15;
            uint4 v4 = reinterpret_cast<const uint4*>(&stg[tl][0])[ch];
            reinterpret_cast<uint4*>(&g_XSb[((size_t)(t0 + tl) * BB + b) * HD])[ch] = v4;
        }
        __syncthreads();
    }
    if (o < 6) present[b * 6 + o] = p[o][TT - 1];
}

// ---------------- fused encoder scan: x-mma pipelined one step ahead ----------------
__global__ __launch_bounds__(512, 1) void enc_scan(const uint32_t* __restrict__ Wihg,
                                                   const uint32_t* __restrict__ Whhg,
                                                   const __nv_bfloat16* __restrict__ XS,
                                                   const float* __restrict__ bih,
                                                   const float* __restrict__ bhh,
                                                   __nv_bfloat16* __restrict__ hstate) {
    extern __shared__ uint32_t smu[];
    uint32_t* Wih = smu;            // 24576
    uint32_t* Whh = smu + 24576;    // 24576
    uint32_t* xs = smu + 49152;     // 4096 (64 rows x 64 u32, XOR-swizzled)
    uint32_t* hb = smu + 53248;     // 4096
    int tid = threadIdx.x;
    int lane = tid & 31, w = tid >> 5;
    int mw = w >> 3, nw = w & 7;
    int lq = lane >> 2, lr = lane & 3;
    int mat = lane >> 3, r8 = lane & 7;
    int m0 = blockIdx.x * 64;
    int gtid = tid & 255;

    for (int idx = tid; idx < 24576 / 4; idx += 512) {
        reinterpret_cast<uint4*>(Wih)[idx] = reinterpret_cast<const uint4*>(Wihg)[idx];
        reinterpret_cast<uint4*>(Whh)[idx] = reinterpret_cast<const uint4*>(Whhg)[idx];
    }
    for (int idx = tid; idx < 4096; idx += 512) hb[idx] = 0u;

    float brz[2][4], bihn[2][2], bhhn[2][2];
#pragma unroll
    for (int jj = 0; jj < 2; jj++) {
        int u = nw * 16 + jj * 8 + lr * 2;
        brz[jj][0] = bih[u] + bhh[u];
        brz[jj][1] = bih[u + 1] + bhh[u + 1];
        brz[jj][2] = bih[u + 128] + bhh[u + 128];
        brz[jj][3] = bih[u + 129] + bhh[u + 129];
        bihn[jj][0] = bih[u + 256]; bihn[jj][1] = bih[u + 257];
        bhhn[jj][0] = bhh[u + 256]; bhhn[jj][1] = bhh[u + 257];
    }

    int row0 = mw * 32 + (mat & 1) * 8 + r8;
    int row1 = row0 + 16;
    int rs = row0 & 7;
    int cm = mat >> 1;
    unsigned xs0 = s2u(xs) + row0 * 256, xs1 = s2u(xs) + row1 * 256;
    unsigned hbb0 = s2u(hb) + row0 * 256, hbb1 = s2u(hb) + row1 * 256;
    unsigned wbih = s2u(Wih) + bpl(lane);
    unsigned wbhh = s2u(Whh) + bpl(lane);

    int pfrow = mw * 32 + (gtid >> 3);
    int pfc = (gtid & 7) * 2;
    int prs = pfrow & 7;
    uint32_t* pfd0 = xs + pfrow * 64 + ((pfc ^ prs) << 2);
    uint32_t* pfd1 = xs + pfrow * 64 + (((pfc + 1) ^ prs) << 2);

    {   // x[0]
        const __nv_bfloat16* gsrc = XS + ((size_t)m0 + pfrow) * HD;
        cpa16(pfd0, gsrc + pfc * 8);
        cpa16(pfd1, gsrc + (pfc + 1) * 8);
        cp_commit();
        cp_wait<0>();
    }

    float hf[16];
#pragma unroll
    for (int i = 0; i < 16; i++) hf[i] = 0.0f;
    __syncthreads();
    if (mw == 1) nsleep(3000);

    float arz[2][4][4], axn[2][2][4], ahn[2][2][4];
#pragma unroll
    for (int i = 0; i < 2; i++) {
#pragma unroll
        for (int j = 0; j < 4; j++)
#pragma unroll
            for (int c = 0; c < 4; c++) arz[i][j][c] = 0.0f;
#pragma unroll
        for (int j = 0; j < 2; j++)
#pragma unroll
            for (int c = 0; c < 4; c++) { axn[i][j][c] = 0.0f; ahn[i][j][c] = 0.0f; }
    }

    // prologue: x-mma(0)
#pragma unroll
    for (int kc = 0; kc < 8; kc++) {
        unsigned sw = (unsigned)(((kc * 2 + cm) ^ rs) << 4);
        unsigned a0[4], a1[4];
        ldsm4(a0, xs0 + sw);
        ldsm4(a1, xs1 + sw);
#pragma unroll
        for (int g = 0; g < 3; g++) {
            int nt0 = g * 16 + nw * 2;
            unsigned b[4];
            ldsm4(b, wbih + (unsigned)((kc * 48 + nt0) * 256));
            float* d00 = (g < 2) ? arz[0][2 * g] : axn[0][0];
            float* d01 = (g < 2) ? arz[0][2 * g + 1] : axn[0][1];
            float* d10 = (g < 2) ? arz[1][2 * g] : axn[1][0];
            float* d11 = (g < 2) ? arz[1][2 * g + 1] : axn[1][1];
            mma16(d00, a0, b[0], b[1]);
            mma16(d01, a0, b[2], b[3]);
            mma16(d10, a1, b[0], b[1]);
            mma16(d11, a1, b[2], b[3]);
        }
    }
    barg(mw);

    for (int t = 0; t < TT; t++) {
        if (t + 1 < TT) {
            const __nv_bfloat16* gsrc = XS + ((size_t)(t + 1) * BB + m0 + pfrow) * HD;
            cpa16(pfd0, gsrc + pfc * 8);
            cpa16(pfd1, gsrc + (pfc + 1) * 8);
            cp_commit();
        }

        // h-mma(t)
#pragma unroll
        for (int kc = 0; kc < 8; kc++) {
            unsigned sw = (unsigned)(((kc * 2 + cm) ^ rs) << 4);
            unsigned a0[4], a1[4];
            ldsm4(a0, hbb0 + sw);
            ldsm4(a1, hbb1 + sw);
#pragma unroll
            for (int g = 0; g < 3; g++) {
                int nt0 = g * 16 + nw * 2;
                unsigned b[4];
                ldsm4(b, wbhh + (unsigned)((kc * 48 + nt0) * 256));
                float* d00 = (g < 2) ? arz[0][2 * g] : ahn[0][0];
                float* d01 = (g < 2) ? arz[0][2 * g + 1] : ahn[0][1];
                float* d10 = (g < 2) ? arz[1][2 * g] : ahn[1][0];
                float* d11 = (g < 2) ? arz[1][2 * g + 1] : ahn[1][1];
                mma16(d00, a0, b[0], b[1]);
                mma16(d01, a0, b[2], b[3]);
                mma16(d10, a1, b[0], b[1]);
                mma16(d11, a1, b[2], b[3]);
            }
        }
        barg(mw);

        // epilogue(t)
#pragma unroll
        for (int jj = 0; jj < 2; jj++) {
            int col = nw * 8 + jj * 4 + lr;
            int csw = col & 3;
            int cch = col >> 2;
#pragma unroll
            for (int i = 0; i < 2; i++) {
#pragma unroll
                for (int h8 = 0; h8 < 2; h8++) {
                    int lrow = mw * 32 + i * 16 + lq + h8 * 8;
                    int ci = h8 * 2;
                    float rx = sigm(arz[i][jj][ci] + brz[jj][0]);
                    float ry = sigm(arz[i][jj][ci + 1] + brz[jj][1]);
                    float zx = sigm(arz[i][jj + 2][ci] + brz[jj][2]);
                    float zy = sigm(arz[i][jj + 2][ci + 1] + brz[jj][3]);
                    float nx = tanha(axn[i][jj][ci] + bihn[jj][0] +
                                     rx * (ahn[i][jj][ci] + bhhn[jj][0]));
                    float ny = tanha(axn[i][jj][ci + 1] + bihn[jj][1] +
                                     ry * (ahn[i][jj][ci + 1] + bhhn[jj][1]));
                    int hx = ((jj * 2 + i) * 2 + h8) * 2;
                    float hxv = nx + zx * (hf[hx] - nx);
                    float hyv = ny + zy * (hf[hx + 1] - ny);
                    hf[hx] = hxv; hf[hx + 1] = hyv;
                    hb[lrow * 64 + ((cch ^ (lrow & 7)) << 2) + csw] = packbf(hxv, hyv);
                }
            }
        }

        if (t + 1 < TT) {
            cp_wait<0>();
#pragma unroll
            for (int i = 0; i < 2; i++) {
#pragma unroll
                for (int j = 0; j < 4; j++)
#pragma unroll
                    for (int c = 0; c < 4; c++) arz[i][j][c] = 0.0f;
#pragma unroll
                for (int j = 0; j < 2; j++)
#pragma unroll
                    for (int c = 0; c < 4; c++) { axn[i][j][c] = 0.0f; ahn[i][j][c] = 0.0f; }
            }
#pragma unroll
            for (int kc = 0; kc < 8; kc++) {
                unsigned sw = (unsigned)(((kc * 2 + cm) ^ rs) << 4);
                unsigned a0[4], a1[4];
                ldsm4(a0, xs0 + sw);
                ldsm4(a1, xs1 + sw);
#pragma unroll
                for (int g = 0; g < 3; g++) {
                    int nt0 = g * 16 + nw * 2;
                    unsigned b[4];
                    ldsm4(b, wbih + (unsigned)((kc * 48 + nt0) * 256));
                    float* d00 = (g < 2) ? arz[0][2 * g] : axn[0][0];
                    float* d01 = (g < 2) ? arz[0][2 * g + 1] : axn[0][1];
                    float* d10 = (g < 2) ? arz[1][2 * g] : axn[1][0];
                    float* d11 = (g < 2) ? arz[1][2 * g + 1] : axn[1][1];
                    mma16(d00, a0, b[0], b[1]);
                    mma16(d01, a0, b[2], b[3]);
                    mma16(d10, a1, b[0], b[1]);
                    mma16(d11, a1, b[2], b[3]);
                }
            }
        }
        barg(mw);
    }

    uint32_t* hsu = reinterpret_cast<uint32_t*>(hstate);
#pragma unroll
    for (int p = 0; p < 8; p++) {
        int idx = gtid + 256 * p;
        int row = mw * 32 + (idx >> 6), c = idx & 63;
        hsu[(size_t)(m0 + row) * 64 + c] = hb[row * 64 + (((c >> 2) ^ (row & 7)) << 2) + (c & 3)];
    }
}

// ---------------- fused decoder scan: step-0 x-mma(hstate@Wih), steps>=1 h-mma ------
__global__ __launch_bounds__(512, 1) void dec_scan(const uint32_t* __restrict__ Wihg,
                                                   const uint32_t* __restrict__ Whhg,
                                                   const __nv_bfloat16* __restrict__ hstate,
                                                   const float* __restrict__ bih,
                                                   const float* __restrict__ bhh,
                                                   uint32_t* __restrict__ hallb) {
    extern __shared__ uint32_t smu[];
    uint32_t* Wih = smu;            // 24576
    uint32_t* Whh = smu + 24576;    // 24576
    uint32_t* hb = smu + 49152;     // 4096
    int tid = threadIdx.x;
    int lane = tid & 31, w = tid >> 5;
    int mw = w >> 3, nw = w & 7;
    int lq = lane >> 2, lr = lane & 3;
    int mat = lane >> 3, r8 = lane & 7;
    int m0 = blockIdx.x * 64;
    int gtid = tid & 255;

    for (int idx = tid; idx < 24576 / 4; idx += 512) {
        reinterpret_cast<uint4*>(Wih)[idx] = reinterpret_cast<const uint4*>(Wihg)[idx];
        reinterpret_cast<uint4*>(Whh)[idx] = reinterpret_cast<const uint4*>(Whhg)[idx];
    }

    float brz[2][4], bihn[2][2], bhhn[2][2];
#pragma unroll
    for (int jj = 0; jj < 2; jj++) {
        int u = nw * 16 + jj * 8 + lr * 2;
        brz[jj][0] = bih[u] + bhh[u];
        brz[jj][1] = bih[u + 1] + bhh[u + 1];
        brz[jj][2] = bih[u + 128] + bhh[u + 128];
        brz[jj][3] = bih[u + 129] + bhh[u + 129];
        bihn[jj][0] = bih[u + 256]; bihn[jj][1] = bih[u + 257];
        bhhn[jj][0] = bhh[u + 256]; bhhn[jj][1] = bhh[u + 257];
    }

    int row0 = mw * 32 + (mat & 1) * 8 + r8;
    int row1 = row0 + 16;
    int rs = row0 & 7;
    int cm = mat >> 1;
    unsigned hbb0 = s2u(hb) + row0 * 256, hbb1 = s2u(hb) + row1 * 256;
    unsigned wbih = s2u(Wih) + bpl(lane);
    unsigned wbhh = s2u(Whh) + bpl(lane);

    {
        int pfrow = mw * 32 + (gtid >> 3);
        int pfc = (gtid & 7) * 2;
        int prs = pfrow & 7;
        const uint32_t* gsrc = reinterpret_cast<const uint32_t*>(hstate) + ((size_t)m0 + pfrow) * 64;
        cpa16(hb + pfrow * 64 + ((pfc ^ prs) << 2), gsrc + pfc * 4);
        cpa16(hb + pfrow * 64 + (((pfc + 1) ^ prs) << 2), gsrc + (pfc + 1) * 4);
        cp_commit();
        cp_wait<0>();
    }

    float hf[16];
#pragma unroll
    for (int i = 0; i < 16; i++) hf[i] = 0.0f;
    __syncthreads();
    if (mw == 1) nsleep(1500);

    for (int s = 0; s < NSTEPS; s++) {
        float arz[2][4][4], an[2][2][4];
#pragma unroll
        for (int i = 0; i < 2; i++) {
#pragma unroll
            for (int j = 0; j < 4; j++)
#pragma unroll
                for (int c = 0; c < 4; c++) arz[i][j][c] = 0.0f;
#pragma unroll
            for (int j = 0; j < 2; j++)
#pragma unroll
                for (int c = 0; c < 4; c++) an[i][j][c] = 0.0f;
        }
        unsigned wb = (s == 0) ? wbih : wbhh;
#pragma unroll
        for (int kc = 0; kc < 8; kc++) {
            unsigned sw = (unsigned)(((kc * 2 + cm) ^ rs) << 4);
            unsigned a0[4], a1[4];
            ldsm4(a0, hbb0 + sw);
            ldsm4(a1, hbb1 + sw);
#pragma unroll
            for (int g = 0; g < 3; g++) {
                int nt0 = g * 16 + nw * 2;
                unsigned b[4];
                ldsm4(b, wb + (unsigned)((kc * 48 + nt0) * 256));
                float* d00 = (g < 2) ? arz[0][2 * g] : an[0][0];
                float* d01 = (g < 2) ? arz[0][2 * g + 1] : an[0][1];
                float* d10 = (g < 2) ? arz[1][2 * g] : an[1][0];
                float* d11 = (g < 2) ? arz[1][2 * g + 1] : an[1][1];
                mma16(d00, a0, b[0], b[1]);
                mma16(d01, a0, b[2], b[3]);
                mma16(d10, a1, b[0], b[1]);
                mma16(d11, a1, b[2], b[3]);
            }
        }
        barg(mw);

#pragma unroll
        for (int jj = 0; jj < 2; jj++) {
            int col = nw * 8 + jj * 4 + lr;
            int csw = col & 3;
            int cch = col >> 2;
#pragma unroll
            for (int i = 0; i < 2; i++) {
#pragma unroll
                for (int h8 = 0; h8 < 2; h8++) {
                    int lrow = mw * 32 + i * 16 + lq + h8 * 8;
                    int ci = h8 * 2;
                    float rx = sigm(arz[i][jj][ci] + brz[jj][0]);
                    float ry = sigm(arz[i][jj][ci + 1] + brz[jj][1]);
                    float zx = sigm(arz[i][jj + 2][ci] + brz[jj][2]);
                    float zy = sigm(arz[i][jj + 2][ci + 1] + brz[jj][3]);
                    float nx, ny;
                    if (s == 0) {
                        nx = tanha(an[i][jj][ci] + bihn[jj][0] + rx * bhhn[jj][0]);
                        ny = tanha(an[i][jj][ci + 1] + bihn[jj][1] + ry * bhhn[jj][1]);
                    } else {
                        nx = tanha(bihn[jj][0] + rx * (an[i][jj][ci] + bhhn[jj][0]));
                        ny = tanha(bihn[jj][1] + ry * (an[i][jj][ci + 1] + bhhn[jj][1]));
                    }
                    int hx = ((jj * 2 + i) * 2 + h8) * 2;
                    float hxv = nx + zx * (hf[hx] - nx);
                    float hyv = ny + zy * (hf[hx + 1] - ny);
                    hf[hx] = hxv; hf[hx + 1] = hyv;
                    hb[lrow * 64 + ((cch ^ (lrow & 7)) << 2) + csw] = packbf(hxv, hyv);
                }
            }
        }
        barg(mw);

        uint32_t* dst = hallb + ((size_t)s * BB + m0) * 64;
#pragma unroll
        for (int p = 0; p < 8; p++) {
            int idx = gtid + 256 * p;
            int row = mw * 32 + (idx >> 6), c = idx & 63;
            dst[row * 64 + c] = hb[row * 64 + (((c >> 2) ^ (row & 7)) << 2) + (c & 3)];
        }
    }
}

// ---------------- batched MLP (512 threads, 16 warps, one 64-row tile/iter) ---------
// warp grid: mw = w>>3 (two 32-row M halves), nw = w&7 (8 N slices)
__global__ __launch_bounds__(512, 1) void mlp_batch(
    const __nv_bfloat16* __restrict__ hall,
    const uint32_t* __restrict__ F1g, const uint32_t* __restrict__ F2g,
    const float* __restrict__ fc1b, const float* __restrict__ fc2b,
    const float* __restrict__ fc3w, const float* __restrict__ fc3b,
    float* __restrict__ inc, int ntiles) {
    extern __shared__ uint32_t smu[];
    uint32_t* F1 = smu;                  // 16384
    uint32_t* F2 = smu + 16384;          // 8192
    uint32_t* As = smu + 24576;          // 2 x 64*68
    uint32_t* A1 = smu + 33280;          // 64*132
    float* A2T = (float*)(smu + 41728);  // 65*64
    float* B1 = (float*)(smu + 45888);
    float* B2 = (float*)(smu + 46144);
    float* B3W = (float*)(smu + 46208);
    float* B3 = (float*)(smu + 46592);   // end 46598 u32 = 186392 B

    int tid = threadIdx.x;
    int lane = tid & 31, w = tid >> 5;
    int mw = w >> 3, nw = w & 7, lq = lane >> 2, lr = lane & 3;
    int mat = lane >> 3, r8 = lane & 7;

    for (int i = tid; i < 16384; i += 512) F1[i] = F1g[i];
    for (int i = tid; i < 8192; i += 512) F2[i] = F2g[i];
    if (tid < 256) B1[tid] = fc1b[tid];
    if (tid < 64) B2[tid] = fc2b[tid];
    if (tid < 6) B3[tid] = fc3b[tid];
    if (tid < 384) B3W[tid] = fc3w[tid];

    unsigned asb = s2u(As + (mw * 32 + (mat & 1) * 8 + r8) * 68 + (mat >> 1) * 4);
    unsigned a1b0 = s2u(A1 + (mw * 32 + (mat & 1) * 8 + r8) * 132 + (mat >> 1) * 4);
    unsigned a1b1 = a1b0 + 16 * 132 * 4;
    unsigned f1b = s2u(F1) + bpl(lane);
    unsigned f2b = s2u(F2) + bpl(lane);

    int grid = gridDim.x;
    int tile0 = blockIdx.x;
    if (tile0 < ntiles) {
#pragma unroll
        for (int j = 0; j < 2; j++) {
            int idx = tid + 512 * j, row = idx >> 4, c = idx & 15;
            cpa16(As + row * 68 + c * 4, hall + ((size_t)tile0 * 64 + row) * HD + c * 8);
        }
        cp_commit();
    }
    __syncthreads();

    int it = 0;
    for (int tile = tile0; tile < ntiles; tile += grid, it++) {
        int nxt = tile + grid;
        if (nxt < ntiles) {
            uint32_t* xb = As + ((it + 1) & 1) * 4352;
#pragma unroll
            for (int j = 0; j < 2; j++) {
                int idx = tid + 512 * j, row = idx >> 4, c = idx & 15;
                cpa16(xb + row * 68 + c * 4, hall + ((size_t)nxt * 64 + row) * HD + c * 8);
            }
            cp_commit();
            cp_wait<1>();
        } else {
            cp_wait<0>();
        }
        __syncthreads();  // cur tile visible; A1/A2T free

        unsigned ab0 = asb + (unsigned)((it & 1) * 4352 * 4);
        unsigned ab1 = ab0 + 16 * 68 * 4;

        // fc1: 64x256 = relu(h @ fc1^T + b1) -> A1 (bf16). Warp: 4 n-tiles.
        float acc1[2][4][4];
#pragma unroll
        for (int i = 0; i < 2; i++)
#pragma unroll
            for (int j = 0; j < 4; j++)
#pragma unroll
                for (int c = 0; c < 4; c++) acc1[i][j][c] = 0.0f;
#pragma unroll
        for (int kc = 0; kc < 8; kc++) {
            unsigned a0[4], a1r[4];
            ldsm4(a0, ab0 + kc * 32);
            ldsm4(a1r, ab1 + kc * 32);
#pragma unroll
            for (int p = 0; p < 2; p++) {
                int nt0 = nw * 4 + 2 * p;
                unsigned b[4];
                ldsm4(b, f1b + (unsigned)((kc * 32 + nt0) * 256));
                mma16(acc1[0][2 * p], a0, b[0], b[1]);
                mma16(acc1[0][2 * p + 1], a0, b[2], b[3]);
                mma16(acc1[1][2 * p], a1r, b[0], b[1]);
                mma16(acc1[1][2 * p + 1], a1r, b[2], b[3]);
            }
        }
#pragma unroll
        for (int j2 = 0; j2 < 4; j2++) {
            int col = nw * 32 + j2 * 8 + lr * 2;
            float2 bb = ld2(B1 + col);
#pragma unroll
            for (int i = 0; i < 2; i++) {
                int row = mw * 32 + i * 16 + lq;
                A1[row * 132 + (col >> 1)] =
                    packbf(fmaxf(acc1[i][j2][0] + bb.x, 0.0f), fmaxf(acc1[i][j2][1] + bb.y, 0.0f));
                A1[(row + 8) * 132 + (col >> 1)] =
                    packbf(fmaxf(acc1[i][j2][2] + bb.x, 0.0f), fmaxf(acc1[i][j2][3] + bb.y, 0.0f));
            }
        }
        __syncthreads();

        // fc2: 64x64 = A1 @ fc2^T + b2 -> A2T (fp32). Warp: 1 n-tile via b-half select.
        float acc2[2][4];
#pragma unroll
        for (int i = 0; i < 2; i++)
#pragma unroll
            for (int c = 0; c < 4; c++) acc2[i][c] = 0.0f;
        int nt0f2 = nw & ~1;
        bool hi = (nw & 1);
#pragma unroll
        for (int kc = 0; kc < 16; kc++) {
            unsigned a0[4], a1r[4];
            ldsm4(a0, a1b0 + kc * 32);
            ldsm4(a1r, a1b1 + kc * 32);
            unsigned b[4];
            ldsm4(b, f2b + (unsigned)((kc * 8 + nt0f2) * 256));
            unsigned b0 = hi ? b[2] : b[0], b1 = hi ? b[3] : b[1];
            mma16(acc2[0], a0, b0, b1);
            mma16(acc2[1], a1r, b0, b1);
        }
        {
            int col = nw * 8 + lr * 2;
            float2 bb = ld2(B2 + col);
#pragma unroll
            for (int i = 0; i < 2; i++) {
                int row = mw * 32 + i * 16 + lq;
                A2T[col * 65 + row] = acc2[i][0] + bb.x;
                A2T[(col + 1) * 65 + row] = acc2[i][1] + bb.y;
                A2T[col * 65 + row + 8] = acc2[i][2] + bb.x;
                A2T[(col + 1) * 65 + row + 8] = acc2[i][3] + bb.y;
            }
        }
        __syncthreads();

        // fc3 (fp32): inc[tile*64 + r][c]
        if (tid < 384) {
            int r = tid & 63, c = tid >> 6;
            float acc = B3[c];
#pragma unroll
            for (int k = 0; k < 64; k++) acc = fmaf(A2T[k * 65 + r], B3W[c * 64 + k], acc);
            inc[(size_t)(tile * 64 + r) * 6 + c] = acc;
        }
        __syncthreads();  // A2T/A1 free for next tile
    }
}

// present prefix-accumulation + final output (same fp32 order as the old scan)
__global__ void prefix_kernel(const float* __restrict__ inc,
                              const float* __restrict__ present0,
                              float* __restrict__ outp) {
    int i = blockIdx.x * 256 + threadIdx.x;
    if (i < BB * 6) {
        int b = i / 6, c = i % 6;
        float pres = present0[i];
#pragma unroll
        for (int s = 0; s < NSTEPS; s++) {
            pres += inc[((size_t)s * BB + b) * 6 + c];
            outp[(size_t)b * 180 + c * 30 + s] = pres;
        }
    }
}

// ---------------- host ----------------
extern "C" void kernel_launch(void* const* d_in, const int* in_sizes, int n_in,
                              void* d_out, int out_size) {
    const float* past = (const float*)d_in[0];
    const float* conv_w = (const float*)d_in[1];
    const float* conv_b = (const float*)d_in[2];
    const float* bn_gamma = (const float*)d_in[3];
    const float* bn_beta = (const float*)d_in[4];
    const float* bn_mean = (const float*)d_in[5];
    const float* bn_var = (const float*)d_in[6];
    const float* enc_wih = (const float*)d_in[7];
    const float* enc_whh = (const float*)d_in[8];
    const float* enc_bih = (const float*)d_in[9];
    const float* enc_bhh = (const float*)d_in[10];
    const float* dec_wih = (const float*)d_in[11];
    const float* dec_whh = (const float*)d_in[12];
    const float* dec_bih = (const float*)d_in[13];
    const float* dec_bhh = (const float*)d_in[14];
    const float* fc1_w = (const float*)d_in[15];
    const float* fc1_b = (const float*)d_in[16];
    const float* fc2_w = (const float*)d_in[17];
    const float* fc2_b = (const float*)d_in[18];
    const float* fc3_w = (const float*)d_in[19];
    const float* fc3_b = (const float*)d_in[20];
    float* outp = (float*)d_out;

    __nv_bfloat16 *p_XSb, *p_hstateb;
    uint32_t *p_hallb, *p_wencih, *p_wenchh, *p_wdecih, *p_wdechh, *p_fc1tb, *p_fc2tb;
    float* p_present;
    cudaGetSymbolAddress((void**)&p_XSb, g_XSb);
    cudaGetSymbolAddress((void**)&p_hstateb, g_hstateb);
    cudaGetSymbolAddress((void**)&p_hallb, g_hallb);
    cudaGetSymbolAddress((void**)&p_present, g_present);
    cudaGetSymbolAddress((void**)&p_wencih, g_wencih);
    cudaGetSymbolAddress((void**)&p_wenchh, g_wenchh);
    cudaGetSymbolAddress((void**)&p_wdecih, g_wdecih);
    cudaGetSymbolAddress((void**)&p_wdechh, g_wdechh);
    cudaGetSymbolAddress((void**)&p_fc1tb, g_fc1tb);
    cudaGetSymbolAddress((void**)&p_fc2tb, g_fc2tb);
    float* p_inc = (float*)p_XSb;  // XS dead after enc_scan; reuse as inc scratch

    const int SMEM_ENC = 57344 * 4;   // 229376 B
    const int SMEM_DEC = 53248 * 4;   // 212992 B
    const int SMEM_MLPB = 46598 * 4;  // 186392 B
    cudaFuncSetAttribute(enc_scan, cudaFuncAttributeMaxDynamicSharedMemorySize, SMEM_ENC);
    cudaFuncSetAttribute(dec_scan, cudaFuncAttributeMaxDynamicSharedMemorySize, SMEM_DEC);
    cudaFuncSetAttribute(mlp_batch, cudaFuncAttributeMaxDynamicSharedMemorySize, SMEM_MLPB);

    // launch plan (mlp_batch at my index 3 = validated ncu capture slot)
    prep_conv<<<480 + BB, 256>>>(enc_wih, enc_whh, dec_wih, dec_whh, fc1_w, fc2_w,
                                 past, conv_w, conv_b, bn_gamma, bn_beta, bn_mean,
                                 bn_var, p_present);                                               // 0
    enc_scan<<<BB / 64, 512, SMEM_ENC>>>(p_wencih, p_wenchh, p_XSb, enc_bih, enc_bhh, p_hstateb);  // 1
    dec_scan<<<BB / 64, 512, SMEM_DEC>>>(p_wdecih, p_wdechh, p_hstateb, dec_bih, dec_bhh, p_hallb);// 2
    mlp_batch<<<148, 512, SMEM_MLPB>>>((const __nv_bfloat16*)p_hallb, p_fc1tb, p_fc2tb,
                                       fc1_b, fc2_b, fc3_w, fc3_b, p_inc, NSTEPS * BB / 64);       // 3 (profiled)
    prefix_kernel<<<(BB * 6 + 255) / 256, 256>>>(p_inc, p_present, outp);                          // 4
}

// round 15
// speedup vs baseline: 1.0304x; 1.0304x over previous
#include <cuda_runtime.h>
#include <cuda_bf16.h>
#include <math.h>
#include <stdint.h>

#define BB 8192
#define TT 128
#define HD 128
#define GG 384
#define NSTEPS 30

typedef unsigned long long ull;

// ---------------- device scratch (static; no allocations allowed) ----------------
__device__ __nv_bfloat16 g_XSb[(size_t)TT * BB * HD];     // 256 MB; reused as fp32 inc later
__device__ __nv_bfloat16 g_hstateb[(size_t)BB * HD];      // encoder final state (bf16)
__device__ uint32_t g_hallb[(size_t)NSTEPS * BB * 64];    // decoder h per step (bf16x2)
__device__ float g_present[(size_t)BB * 6];
__device__ uint32_t g_wencih[24576];                      // ldsm-ready B fragment tiles
__device__ uint32_t g_wenchh[24576];
__device__ uint32_t g_wdecih[24576];
__device__ uint32_t g_wdechh[24576];
__device__ uint32_t g_fc1tb[16384];
__device__ uint32_t g_fc2tb[8192];

// ---------------- helpers ----------------
__device__ __forceinline__ uint32_t packbf(float x, float y) {
    __nv_bfloat162 v = __floats2bfloat162_rn(x, y);
    return *reinterpret_cast<uint32_t*>(&v);
}
__device__ __forceinline__ void mma16(float* d, const unsigned* a, unsigned b0, unsigned b1) {
    asm volatile(
        "mma.sync.aligned.m16n8k16.row.col.f32.bf16.bf16.f32 "
        "{%0,%1,%2,%3}, {%4,%5,%6,%7}, {%8,%9}, {%0,%1,%2,%3};"
        : "+f"(d[0]), "+f"(d[1]), "+f"(d[2]), "+f"(d[3])
        : "r"(a[0]), "r"(a[1]), "r"(a[2]), "r"(a[3]), "r"(b0), "r"(b1));
}
__device__ __forceinline__ unsigned s2u(const void* p) {
    return (unsigned)__cvta_generic_to_shared(p);
}
__device__ __forceinline__ void ldsm4(unsigned a[4], unsigned saddr) {
    asm volatile("ldmatrix.sync.aligned.m8n8.x4.shared.b16 {%0,%1,%2,%3}, [%4];"
                 : "=r"(a[0]), "=r"(a[1]), "=r"(a[2]), "=r"(a[3]) : "r"(saddr));
}
__device__ __forceinline__ float sigm(float x) {
    float t; asm("tanh.approx.f32 %0, %1;" : "=f"(t) : "f"(x * 0.5f));
    return fmaf(t, 0.5f, 0.5f);
}
__device__ __forceinline__ float tanha(float x) {
    float t; asm("tanh.approx.f32 %0, %1;" : "=f"(t) : "f"(x));
    return t;
}
__device__ __forceinline__ float2 ld2(const float* p) { return *reinterpret_cast<const float2*>(p); }
__device__ __forceinline__ void barg(int grp) {
    asm volatile("bar.sync %0, 256;" :: "r"(grp + 1) : "memory");
}
__device__ __forceinline__ void nsleep(unsigned ns) {
    asm volatile("nanosleep.u32 %0;" :: "r"(ns));
}

// cp.async
__device__ __forceinline__ void cpa16(void* smem, const void* g) {
    unsigned saddr = s2u(smem);
    asm volatile("cp.async.cg.shared.global [%0], [%1], 16;" :: "r"(saddr), "l"(g));
}
__device__ __forceinline__ void cp_commit() { asm volatile("cp.async.commit_group;"); }
template <int N> __device__ __forceinline__ void cp_wait() {
    asm volatile("cp.async.wait_group %0;" :: "n"(N));
}

// per-lane byte offset inside a 512B B-tile-pair block for ldsm.x4
__device__ __forceinline__ unsigned bpl(int lane) {
    return ((unsigned)(lane >> 3) << 7) | ((unsigned)(lane & 7) << 4);
}

// ---------------- prep: ldsm-pair B layout (standalone, 480 x 256) ----------------
__global__ void prep_all(const float* __restrict__ ewih, const float* __restrict__ ewhh,
                         const float* __restrict__ dwih, const float* __restrict__ dwhh,
                         const float* __restrict__ f1w, const float* __restrict__ f2w) {
    int b = blockIdx.x, tid = threadIdx.x;
    if (b < 384) {
        int wsel = b / 96;
        const float* src = (wsel == 0) ? ewih : (wsel == 1) ? ewhh : (wsel == 2) ? dwih : dwhh;
        uint32_t* dst = (wsel == 0) ? g_wencih : (wsel == 1) ? g_wenchh : (wsel == 2) ? g_wdecih : g_wdechh;
        int e = (b % 96) * 256 + tid;
        int n = e >> 6, k2 = e & 63;
        uint32_t v = packbf(src[n * HD + 2 * k2], src[n * HD + 2 * k2 + 1]);
        int pos = ((k2 >> 2) & 1) * 32 + ((n & 7) << 2) + (k2 & 3);
        dst[((k2 >> 3) * 48 + (n >> 3)) * 64 + pos] = v;
    } else if (b < 448) {
        int e = (b - 384) * 256 + tid;
        int n = e >> 6, k2 = e & 63;
        uint32_t v = packbf(f1w[n * 128 + 2 * k2], f1w[n * 128 + 2 * k2 + 1]);
        int pos = ((k2 >> 2) & 1) * 32 + ((n & 7) << 2) + (k2 & 3);
        g_fc1tb[((k2 >> 3) * 32 + (n >> 3)) * 64 + pos] = v;
    } else {
        int e = (b - 448) * 256 + tid;
        int n = e >> 7, k2 = e & 127;
        uint32_t v = packbf(f2w[n * 256 + 2 * k2], f2w[n * 256 + 2 * k2 + 1]);
        int pos = ((k2 >> 2) & 1) * 32 + ((n & 7) << 2) + (k2 & 3);
        g_fc2tb[((k2 >> 3) * 8 + (n >> 3)) * 64 + pos] = v;
    }
}

// conv1d(6->128,k=3,pad=1)+bias+relu+BN -> XS bf16 (128 threads, R13 config); present0
__global__ void conv_bn_kernel(const float* __restrict__ past, const float* __restrict__ cw,
                               const float* __restrict__ cb, const float* __restrict__ bng,
                               const float* __restrict__ bnb, const float* __restrict__ bnm,
                               const float* __restrict__ bnv, float* __restrict__ present) {
    __shared__ float p[6][TT];
    __shared__ __nv_bfloat16 stg[8][HD];
    int b = blockIdx.x, o = threadIdx.x;
    for (int i = o; i < 6 * TT; i += HD) p[i / TT][i % TT] = past[(size_t)b * 6 * TT + i];
    float w[6][3];
#pragma unroll
    for (int i = 0; i < 6; i++)
#pragma unroll
        for (int k = 0; k < 3; k++) w[i][k] = cw[(o * 6 + i) * 3 + k];
    float bias = cb[o];
    float scale = bng[0] * rsqrtf(bnv[0] + 1e-5f);
    float shift = bnb[0] - bnm[0] * scale;
    __syncthreads();
    for (int t0 = 0; t0 < TT; t0 += 8) {
#pragma unroll
        for (int t2 = 0; t2 < 8; t2++) {
            int t = t0 + t2;
            float acc = bias;
#pragma unroll
            for (int i = 0; i < 6; i++) {
                float l = (t > 0) ? p[i][t - 1] : 0.0f;
                float r = (t < TT - 1) ? p[i][t + 1] : 0.0f;
                acc += l * w[i][0] + p[i][t] * w[i][1] + r * w[i][2];
            }
            float v = fmaxf(acc, 0.0f) * scale + shift;
            stg[t2][o] = __float2bfloat16(v);
        }
        __syncthreads();
        {
            int tl = o >> 4, ch = o & 15;
            uint4 v4 = reinterpret_cast<const uint4*>(&stg[tl][0])[ch];
            reinterpret_cast<uint4*>(&g_XSb[((size_t)(t0 + tl) * BB + b) * HD])[ch] = v4;
        }
        __syncthreads();
    }
    if (o < 6) present[b * 6 + o] = p[o][TT - 1];
}

// ---------------- fused encoder scan: x-mma pipelined one step ahead ----------------
__global__ __launch_bounds__(512, 1) void enc_scan(const uint32_t* __restrict__ Wihg,
                                                   const uint32_t* __restrict__ Whhg,
                                                   const __nv_bfloat16* __restrict__ XS,
                                                   const float* __restrict__ bih,
                                                   const float* __restrict__ bhh,
                                                   __nv_bfloat16* __restrict__ hstate) {
    extern __shared__ uint32_t smu[];
    uint32_t* Wih = smu;            // 24576
    uint32_t* Whh = smu + 24576;    // 24576
    uint32_t* xs = smu + 49152;     // 4096 (64 rows x 64 u32, XOR-swizzled)
    uint32_t* hb = smu + 53248;     // 4096
    int tid = threadIdx.x;
    int lane = tid & 31, w = tid >> 5;
    int mw = w >> 3, nw = w & 7;
    int lq = lane >> 2, lr = lane & 3;
    int mat = lane >> 3, r8 = lane & 7;
    int m0 = blockIdx.x * 64;
    int gtid = tid & 255;

    for (int idx = tid; idx < 24576 / 4; idx += 512) {
        reinterpret_cast<uint4*>(Wih)[idx] = reinterpret_cast<const uint4*>(Wihg)[idx];
        reinterpret_cast<uint4*>(Whh)[idx] = reinterpret_cast<const uint4*>(Whhg)[idx];
    }
    for (int idx = tid; idx < 4096; idx += 512) hb[idx] = 0u;

    float brz[2][4], bihn[2][2], bhhn[2][2];
#pragma unroll
    for (int jj = 0; jj < 2; jj++) {
        int u = nw * 16 + jj * 8 + lr * 2;
        brz[jj][0] = bih[u] + bhh[u];
        brz[jj][1] = bih[u + 1] + bhh[u + 1];
        brz[jj][2] = bih[u + 128] + bhh[u + 128];
        brz[jj][3] = bih[u + 129] + bhh[u + 129];
        bihn[jj][0] = bih[u + 256]; bihn[jj][1] = bih[u + 257];
        bhhn[jj][0] = bhh[u + 256]; bhhn[jj][1] = bhh[u + 257];
    }

    int row0 = mw * 32 + (mat & 1) * 8 + r8;
    int row1 = row0 + 16;
    int rs = row0 & 7;
    int cm = mat >> 1;
    unsigned xs0 = s2u(xs) + row0 * 256, xs1 = s2u(xs) + row1 * 256;
    unsigned hbb0 = s2u(hb) + row0 * 256, hbb1 = s2u(hb) + row1 * 256;
    unsigned wbih = s2u(Wih) + bpl(lane);
    unsigned wbhh = s2u(Whh) + bpl(lane);

    int pfrow = mw * 32 + (gtid >> 3);
    int pfc = (gtid & 7) * 2;
    int prs = pfrow & 7;
    uint32_t* pfd0 = xs + pfrow * 64 + ((pfc ^ prs) << 2);
    uint32_t* pfd1 = xs + pfrow * 64 + (((pfc + 1) ^ prs) << 2);

    {   // x[0]
        const __nv_bfloat16* gsrc = XS + ((size_t)m0 + pfrow) * HD;
        cpa16(pfd0, gsrc + pfc * 8);
        cpa16(pfd1, gsrc + (pfc + 1) * 8);
        cp_commit();
        cp_wait<0>();
    }

    float hf[16];
#pragma unroll
    for (int i = 0; i < 16; i++) hf[i] = 0.0f;
    __syncthreads();
    if (mw == 1) nsleep(3000);

    float arz[2][4][4], axn[2][2][4], ahn[2][2][4];
#pragma unroll
    for (int i = 0; i < 2; i++) {
#pragma unroll
        for (int j = 0; j < 4; j++)
#pragma unroll
            for (int c = 0; c < 4; c++) arz[i][j][c] = 0.0f;
#pragma unroll
        for (int j = 0; j < 2; j++)
#pragma unroll
            for (int c = 0; c < 4; c++) { axn[i][j][c] = 0.0f; ahn[i][j][c] = 0.0f; }
    }

    // prologue: x-mma(0)
#pragma unroll
    for (int kc = 0; kc < 8; kc++) {
        unsigned sw = (unsigned)(((kc * 2 + cm) ^ rs) << 4);
        unsigned a0[4], a1[4];
        ldsm4(a0, xs0 + sw);
        ldsm4(a1, xs1 + sw);
#pragma unroll
        for (int g = 0; g < 3; g++) {
            int nt0 = g * 16 + nw * 2;
            unsigned b[4];
            ldsm4(b, wbih + (unsigned)((kc * 48 + nt0) * 256));
            float* d00 = (g < 2) ? arz[0][2 * g] : axn[0][0];
            float* d01 = (g < 2) ? arz[0][2 * g + 1] : axn[0][1];
            float* d10 = (g < 2) ? arz[1][2 * g] : axn[1][0];
            float* d11 = (g < 2) ? arz[1][2 * g + 1] : axn[1][1];
            mma16(d00, a0, b[0], b[1]);
            mma16(d01, a0, b[2], b[3]);
            mma16(d10, a1, b[0], b[1]);
            mma16(d11, a1, b[2], b[3]);
        }
    }
    barg(mw);

    for (int t = 0; t < TT; t++) {
        if (t + 1 < TT) {
            const __nv_bfloat16* gsrc = XS + ((size_t)(t + 1) * BB + m0 + pfrow) * HD;
            cpa16(pfd0, gsrc + pfc * 8);
            cpa16(pfd1, gsrc + (pfc + 1) * 8);
            cp_commit();
        }

        // h-mma(t)
#pragma unroll
        for (int kc = 0; kc < 8; kc++) {
            unsigned sw = (unsigned)(((kc * 2 + cm) ^ rs) << 4);
            unsigned a0[4], a1[4];
            ldsm4(a0, hbb0 + sw);
            ldsm4(a1, hbb1 + sw);
#pragma unroll
            for (int g = 0; g < 3; g++) {
                int nt0 = g * 16 + nw * 2;
                unsigned b[4];
                ldsm4(b, wbhh + (unsigned)((kc * 48 + nt0) * 256));
                float* d00 = (g < 2) ? arz[0][2 * g] : ahn[0][0];
                float* d01 = (g < 2) ? arz[0][2 * g + 1] : ahn[0][1];
                float* d10 = (g < 2) ? arz[1][2 * g] : ahn[1][0];
                float* d11 = (g < 2) ? arz[1][2 * g + 1] : ahn[1][1];
                mma16(d00, a0, b[0], b[1]);
                mma16(d01, a0, b[2], b[3]);
                mma16(d10, a1, b[0], b[1]);
                mma16(d11, a1, b[2], b[3]);
            }
        }
        barg(mw);

        // epilogue(t)
#pragma unroll
        for (int jj = 0; jj < 2; jj++) {
            int col = nw * 8 + jj * 4 + lr;
            int csw = col & 3;
            int cch = col >> 2;
#pragma unroll
            for (int i = 0; i < 2; i++) {
#pragma unroll
                for (int h8 = 0; h8 < 2; h8++) {
                    int lrow = mw * 32 + i * 16 + lq + h8 * 8;
                    int ci = h8 * 2;
                    float rx = sigm(arz[i][jj][ci] + brz[jj][0]);
                    float ry = sigm(arz[i][jj][ci + 1] + brz[jj][1]);
                    float zx = sigm(arz[i][jj + 2][ci] + brz[jj][2]);
                    float zy = sigm(arz[i][jj + 2][ci + 1] + brz[jj][3]);
                    float nx = tanha(axn[i][jj][ci] + bihn[jj][0] +
                                     rx * (ahn[i][jj][ci] + bhhn[jj][0]));
                    float ny = tanha(axn[i][jj][ci + 1] + bihn[jj][1] +
                                     ry * (ahn[i][jj][ci + 1] + bhhn[jj][1]));
                    int hx = ((jj * 2 + i) * 2 + h8) * 2;
                    float hxv = nx + zx * (hf[hx] - nx);
                    float hyv = ny + zy * (hf[hx + 1] - ny);
                    hf[hx] = hxv; hf[hx + 1] = hyv;
                    hb[lrow * 64 + ((cch ^ (lrow & 7)) << 2) + csw] = packbf(hxv, hyv);
                }
            }
        }

        if (t + 1 < TT) {
            cp_wait<0>();
#pragma unroll
            for (int i = 0; i < 2; i++) {
#pragma unroll
                for (int j = 0; j < 4; j++)
#pragma unroll
                    for (int c = 0; c < 4; c++) arz[i][j][c] = 0.0f;
#pragma unroll
                for (int j = 0; j < 2; j++)
#pragma unroll
                    for (int c = 0; c < 4; c++) { axn[i][j][c] = 0.0f; ahn[i][j][c] = 0.0f; }
            }
#pragma unroll
            for (int kc = 0; kc < 8; kc++) {
                unsigned sw = (unsigned)(((kc * 2 + cm) ^ rs) << 4);
                unsigned a0[4], a1[4];
                ldsm4(a0, xs0 + sw);
                ldsm4(a1, xs1 + sw);
#pragma unroll
                for (int g = 0; g < 3; g++) {
                    int nt0 = g * 16 + nw * 2;
                    unsigned b[4];
                    ldsm4(b, wbih + (unsigned)((kc * 48 + nt0) * 256));
                    float* d00 = (g < 2) ? arz[0][2 * g] : axn[0][0];
                    float* d01 = (g < 2) ? arz[0][2 * g + 1] : axn[0][1];
                    float* d10 = (g < 2) ? arz[1][2 * g] : axn[1][0];
                    float* d11 = (g < 2) ? arz[1][2 * g + 1] : axn[1][1];
                    mma16(d00, a0, b[0], b[1]);
                    mma16(d01, a0, b[2], b[3]);
                    mma16(d10, a1, b[0], b[1]);
                    mma16(d11, a1, b[2], b[3]);
                }
            }
        }
        barg(mw);
    }

    uint32_t* hsu = reinterpret_cast<uint32_t*>(hstate);
#pragma unroll
    for (int p = 0; p < 8; p++) {
        int idx = gtid + 256 * p;
        int row = mw * 32 + (idx >> 6), c = idx & 63;
        hsu[(size_t)(m0 + row) * 64 + c] = hb[row * 64 + (((c >> 2) ^ (row & 7)) << 2) + (c & 3)];
    }
}

// ---------------- fused decoder scan: step-0 x-mma(hstate@Wih), steps>=1 h-mma ------
__global__ __launch_bounds__(512, 1) void dec_scan(const uint32_t* __restrict__ Wihg,
                                                   const uint32_t* __restrict__ Whhg,
                                                   const __nv_bfloat16* __restrict__ hstate,
                                                   const float* __restrict__ bih,
                                                   const float* __restrict__ bhh,
                                                   uint32_t* __restrict__ hallb) {
    extern __shared__ uint32_t smu[];
    uint32_t* Wih = smu;            // 24576
    uint32_t* Whh = smu + 24576;    // 24576
    uint32_t* hb = smu + 49152;     // 4096
    int tid = threadIdx.x;
    int lane = tid & 31, w = tid >> 5;
    int mw = w >> 3, nw = w & 7;
    int lq = lane >> 2, lr = lane & 3;
    int mat = lane >> 3, r8 = lane & 7;
    int m0 = blockIdx.x * 64;
    int gtid = tid & 255;

    for (int idx = tid; idx < 24576 / 4; idx += 512) {
        reinterpret_cast<uint4*>(Wih)[idx] = reinterpret_cast<const uint4*>(Wihg)[idx];
        reinterpret_cast<uint4*>(Whh)[idx] = reinterpret_cast<const uint4*>(Whhg)[idx];
    }

    float brz[2][4], bihn[2][2], bhhn[2][2];
#pragma unroll
    for (int jj = 0; jj < 2; jj++) {
        int u = nw * 16 + jj * 8 + lr * 2;
        brz[jj][0] = bih[u] + bhh[u];
        brz[jj][1] = bih[u + 1] + bhh[u + 1];
        brz[jj][2] = bih[u + 128] + bhh[u + 128];
        brz[jj][3] = bih[u + 129] + bhh[u + 129];
        bihn[jj][0] = bih[u + 256]; bihn[jj][1] = bih[u + 257];
        bhhn[jj][0] = bhh[u + 256]; bhhn[jj][1] = bhh[u + 257];
    }

    int row0 = mw * 32 + (mat & 1) * 8 + r8;
    int row1 = row0 + 16;
    int rs = row0 & 7;
    int cm = mat >> 1;
    unsigned hbb0 = s2u(hb) + row0 * 256, hbb1 = s2u(hb) + row1 * 256;
    unsigned wbih = s2u(Wih) + bpl(lane);
    unsigned wbhh = s2u(Whh) + bpl(lane);

    {
        int pfrow = mw * 32 + (gtid >> 3);
        int pfc = (gtid & 7) * 2;
        int prs = pfrow & 7;
        const uint32_t* gsrc = reinterpret_cast<const uint32_t*>(hstate) + ((size_t)m0 + pfrow) * 64;
        cpa16(hb + pfrow * 64 + ((pfc ^ prs) << 2), gsrc + pfc * 4);
        cpa16(hb + pfrow * 64 + (((pfc + 1) ^ prs) << 2), gsrc + (pfc + 1) * 4);
        cp_commit();
        cp_wait<0>();
    }

    float hf[16];
#pragma unroll
    for (int i = 0; i < 16; i++) hf[i] = 0.0f;
    __syncthreads();
    if (mw == 1) nsleep(1500);

    for (int s = 0; s < NSTEPS; s++) {
        float arz[2][4][4], an[2][2][4];
#pragma unroll
        for (int i = 0; i < 2; i++) {
#pragma unroll
            for (int j = 0; j < 4; j++)
#pragma unroll
                for (int c = 0; c < 4; c++) arz[i][j][c] = 0.0f;
#pragma unroll
            for (int j = 0; j < 2; j++)
#pragma unroll
                for (int c = 0; c < 4; c++) an[i][j][c] = 0.0f;
        }
        unsigned wb = (s == 0) ? wbih : wbhh;
#pragma unroll
        for (int kc = 0; kc < 8; kc++) {
            unsigned sw = (unsigned)(((kc * 2 + cm) ^ rs) << 4);
            unsigned a0[4], a1[4];
            ldsm4(a0, hbb0 + sw);
            ldsm4(a1, hbb1 + sw);
#pragma unroll
            for (int g = 0; g < 3; g++) {
                int nt0 = g * 16 + nw * 2;
                unsigned b[4];
                ldsm4(b, wb + (unsigned)((kc * 48 + nt0) * 256));
                float* d00 = (g < 2) ? arz[0][2 * g] : an[0][0];
                float* d01 = (g < 2) ? arz[0][2 * g + 1] : an[0][1];
                float* d10 = (g < 2) ? arz[1][2 * g] : an[1][0];
                float* d11 = (g < 2) ? arz[1][2 * g + 1] : an[1][1];
                mma16(d00, a0, b[0], b[1]);
                mma16(d01, a0, b[2], b[3]);
                mma16(d10, a1, b[0], b[1]);
                mma16(d11, a1, b[2], b[3]);
            }
        }
        barg(mw);

#pragma unroll
        for (int jj = 0; jj < 2; jj++) {
            int col = nw * 8 + jj * 4 + lr;
            int csw = col & 3;
            int cch = col >> 2;
#pragma unroll
            for (int i = 0; i < 2; i++) {
#pragma unroll
                for (int h8 = 0; h8 < 2; h8++) {
                    int lrow = mw * 32 + i * 16 + lq + h8 * 8;
                    int ci = h8 * 2;
                    float rx = sigm(arz[i][jj][ci] + brz[jj][0]);
                    float ry = sigm(arz[i][jj][ci + 1] + brz[jj][1]);
                    float zx = sigm(arz[i][jj + 2][ci] + brz[jj][2]);
                    float zy = sigm(arz[i][jj + 2][ci + 1] + brz[jj][3]);
                    float nx, ny;
                    if (s == 0) {
                        nx = tanha(an[i][jj][ci] + bihn[jj][0] + rx * bhhn[jj][0]);
                        ny = tanha(an[i][jj][ci + 1] + bihn[jj][1] + ry * bhhn[jj][1]);
                    } else {
                        nx = tanha(bihn[jj][0] + rx * (an[i][jj][ci] + bhhn[jj][0]));
                        ny = tanha(bihn[jj][1] + ry * (an[i][jj][ci + 1] + bhhn[jj][1]));
                    }
                    int hx = ((jj * 2 + i) * 2 + h8) * 2;
                    float hxv = nx + zx * (hf[hx] - nx);
                    float hyv = ny + zy * (hf[hx + 1] - ny);
                    hf[hx] = hxv; hf[hx + 1] = hyv;
                    hb[lrow * 64 + ((cch ^ (lrow & 7)) << 2) + csw] = packbf(hxv, hyv);
                }
            }
        }
        barg(mw);

        uint32_t* dst = hallb + ((size_t)s * BB + m0) * 64;
#pragma unroll
        for (int p = 0; p < 8; p++) {
            int idx = gtid + 256 * p;
            int row = mw * 32 + (idx >> 6), c = idx & 63;
            dst[row * 64 + c] = hb[row * 64 + (((c >> 2) ^ (row & 7)) << 2) + (c & 3)];
        }
    }
}

// ---------------- batched MLP (512 threads, 16 warps; verified 128us in R14) --------
__global__ __launch_bounds__(512, 1) void mlp_batch(
    const __nv_bfloat16* __restrict__ hall,
    const uint32_t* __restrict__ F1g, const uint32_t* __restrict__ F2g,
    const float* __restrict__ fc1b, const float* __restrict__ fc2b,
    const float* __restrict__ fc3w, const float* __restrict__ fc3b,
    float* __restrict__ inc, int ntiles) {
    extern __shared__ uint32_t smu[];
    uint32_t* F1 = smu;                  // 16384
    uint32_t* F2 = smu + 16384;          // 8192
    uint32_t* As = smu + 24576;          // 2 x 64*68
    uint32_t* A1 = smu + 33280;          // 64*132
    float* A2T = (float*)(smu + 41728);  // 65*64
    float* B1 = (float*)(smu + 45888);
    float* B2 = (float*)(smu + 46144);
    float* B3W = (float*)(smu + 46208);
    float* B3 = (float*)(smu + 46592);   // end 46598 u32 = 186392 B

    int tid = threadIdx.x;
    int lane = tid & 31, w = tid >> 5;
    int mw = w >> 3, nw = w & 7, lq = lane >> 2, lr = lane & 3;
    int mat = lane >> 3, r8 = lane & 7;

    for (int i = tid; i < 16384; i += 512) F1[i] = F1g[i];
    for (int i = tid; i < 8192; i += 512) F2[i] = F2g[i];
    if (tid < 256) B1[tid] = fc1b[tid];
    if (tid < 64) B2[tid] = fc2b[tid];
    if (tid < 6) B3[tid] = fc3b[tid];
    if (tid < 384) B3W[tid] = fc3w[tid];

    unsigned asb = s2u(As + (mw * 32 + (mat & 1) * 8 + r8) * 68 + (mat >> 1) * 4);
    unsigned a1b0 = s2u(A1 + (mw * 32 + (mat & 1) * 8 + r8) * 132 + (mat >> 1) * 4);
    unsigned a1b1 = a1b0 + 16 * 132 * 4;
    unsigned f1b = s2u(F1) + bpl(lane);
    unsigned f2b = s2u(F2) + bpl(lane);

    int grid = gridDim.x;
    int tile0 = blockIdx.x;
    if (tile0 < ntiles) {
#pragma unroll
        for (int j = 0; j < 2; j++) {
            int idx = tid + 512 * j, row = idx >> 4, c = idx & 15;
            cpa16(As + row * 68 + c * 4, hall + ((size_t)tile0 * 64 + row) * HD + c * 8);
        }
        cp_commit();
    }
    __syncthreads();

    int it = 0;
    for (int tile = tile0; tile < ntiles; tile += grid, it++) {
        int nxt = tile + grid;
        if (nxt < ntiles) {
            uint32_t* xb = As + ((it + 1) & 1) * 4352;
#pragma unroll
            for (int j = 0; j < 2; j++) {
                int idx = tid + 512 * j, row = idx >> 4, c = idx & 15;
                cpa16(xb + row * 68 + c * 4, hall + ((size_t)nxt * 64 + row) * HD + c * 8);
            }
            cp_commit();
            cp_wait<1>();
        } else {
            cp_wait<0>();
        }
        __syncthreads();  // cur tile visible; A1/A2T free

        unsigned ab0 = asb + (unsigned)((it & 1) * 4352 * 4);
        unsigned ab1 = ab0 + 16 * 68 * 4;

        // fc1: 64x256 = relu(h @ fc1^T + b1) -> A1 (bf16). Warp: 4 n-tiles.
        float acc1[2][4][4];
#pragma unroll
        for (int i = 0; i < 2; i++)
#pragma unroll
            for (int j = 0; j < 4; j++)
#pragma unroll
                for (int c = 0; c < 4; c++) acc1[i][j][c] = 0.0f;
#pragma unroll
        for (int kc = 0; kc < 8; kc++) {
            unsigned a0[4], a1r[4];
            ldsm4(a0, ab0 + kc * 32);
            ldsm4(a1r, ab1 + kc * 32);
#pragma unroll
            for (int p = 0; p < 2; p++) {
                int nt0 = nw * 4 + 2 * p;
                unsigned b[4];
                ldsm4(b, f1b + (unsigned)((kc * 32 + nt0) * 256));
                mma16(acc1[0][2 * p], a0, b[0], b[1]);
                mma16(acc1[0][2 * p + 1], a0, b[2], b[3]);
                mma16(acc1[1][2 * p], a1r, b[0], b[1]);
                mma16(acc1[1][2 * p + 1], a1r, b[2], b[3]);
            }
        }
#pragma unroll
        for (int j2 = 0; j2 < 4; j2++) {
            int col = nw * 32 + j2 * 8 + lr * 2;
            float2 bb = ld2(B1 + col);
#pragma unroll
            for (int i = 0; i < 2; i++) {
                int row = mw * 32 + i * 16 + lq;
                A1[row * 132 + (col >> 1)] =
                    packbf(fmaxf(acc1[i][j2][0] + bb.x, 0.0f), fmaxf(acc1[i][j2][1] + bb.y, 0.0f));
                A1[(row + 8) * 132 + (col >> 1)] =
                    packbf(fmaxf(acc1[i][j2][2] + bb.x, 0.0f), fmaxf(acc1[i][j2][3] + bb.y, 0.0f));
            }
        }
        __syncthreads();

        // fc2: 64x64 = A1 @ fc2^T + b2 -> A2T (fp32). Warp: 1 n-tile via b-half select.
        float acc2[2][4];
#pragma unroll
        for (int i = 0; i < 2; i++)
#pragma unroll
            for (int c = 0; c < 4; c++) acc2[i][c] = 0.0f;
        int nt0f2 = nw & ~1;
        bool hi = (nw & 1);
#pragma unroll
        for (int kc = 0; kc < 16; kc++) {
            unsigned a0[4], a1r[4];
            ldsm4(a0, a1b0 + kc * 32);
            ldsm4(a1r, a1b1 + kc * 32);
            unsigned b[4];
            ldsm4(b, f2b + (unsigned)((kc * 8 + nt0f2) * 256));
            unsigned b0 = hi ? b[2] : b[0], b1 = hi ? b[3] : b[1];
            mma16(acc2[0], a0, b0, b1);
            mma16(acc2[1], a1r, b0, b1);
        }
        {
            int col = nw * 8 + lr * 2;
            float2 bb = ld2(B2 + col);
#pragma unroll
            for (int i = 0; i < 2; i++) {
                int row = mw * 32 + i * 16 + lq;
                A2T[col * 65 + row] = acc2[i][0] + bb.x;
                A2T[(col + 1) * 65 + row] = acc2[i][1] + bb.y;
                A2T[col * 65 + row + 8] = acc2[i][2] + bb.x;
                A2T[(col + 1) * 65 + row + 8] = acc2[i][3] + bb.y;
            }
        }
        __syncthreads();

        // fc3 (fp32): inc[tile*64 + r][c]
        if (tid < 384) {
            int r = tid & 63, c = tid >> 6;
            float acc = B3[c];
#pragma unroll
            for (int k = 0; k < 64; k++) acc = fmaf(A2T[k * 65 + r], B3W[c * 64 + k], acc);
            inc[(size_t)(tile * 64 + r) * 6 + c] = acc;
        }
        __syncthreads();  // A2T/A1 free for next tile
    }
}

// present prefix-accumulation + final output (same fp32 order as the old scan)
__global__ void prefix_kernel(const float* __restrict__ inc,
                              const float* __restrict__ present0,
                              float* __restrict__ outp) {
    int i = blockIdx.x * 256 + threadIdx.x;
    if (i < BB * 6) {
        int b = i / 6, c = i % 6;
        float pres = present0[i];
#pragma unroll
        for (int s = 0; s < NSTEPS; s++) {
            pres += inc[((size_t)s * BB + b) * 6 + c];
            outp[(size_t)b * 180 + c * 30 + s] = pres;
        }
    }
}

// ---------------- host ----------------
extern "C" void kernel_launch(void* const* d_in, const int* in_sizes, int n_in,
                              void* d_out, int out_size) {
    const float* past = (const float*)d_in[0];
    const float* conv_w = (const float*)d_in[1];
    const float* conv_b = (const float*)d_in[2];
    const float* bn_gamma = (const float*)d_in[3];
    const float* bn_beta = (const float*)d_in[4];
    const float* bn_mean = (const float*)d_in[5];
    const float* bn_var = (const float*)d_in[6];
    const float* enc_wih = (const float*)d_in[7];
    const float* enc_whh = (const float*)d_in[8];
    const float* enc_bih = (const float*)d_in[9];
    const float* enc_bhh = (const float*)d_in[10];
    const float* dec_wih = (const float*)d_in[11];
    const float* dec_whh = (const float*)d_in[12];
    const float* dec_bih = (const float*)d_in[13];
    const float* dec_bhh = (const float*)d_in[14];
    const float* fc1_w = (const float*)d_in[15];
    const float* fc1_b = (const float*)d_in[16];
    const float* fc2_w = (const float*)d_in[17];
    const float* fc2_b = (const float*)d_in[18];
    const float* fc3_w = (const float*)d_in[19];
    const float* fc3_b = (const float*)d_in[20];
    float* outp = (float*)d_out;

    __nv_bfloat16 *p_XSb, *p_hstateb;
    uint32_t *p_hallb, *p_wencih, *p_wenchh, *p_wdecih, *p_wdechh, *p_fc1tb, *p_fc2tb;
    float* p_present;
    cudaGetSymbolAddress((void**)&p_XSb, g_XSb);
    cudaGetSymbolAddress((void**)&p_hstateb, g_hstateb);
    cudaGetSymbolAddress((void**)&p_hallb, g_hallb);
    cudaGetSymbolAddress((void**)&p_present, g_present);
    cudaGetSymbolAddress((void**)&p_wencih, g_wencih);
    cudaGetSymbolAddress((void**)&p_wenchh, g_wenchh);
    cudaGetSymbolAddress((void**)&p_wdecih, g_wdecih);
    cudaGetSymbolAddress((void**)&p_wdechh, g_wdechh);
    cudaGetSymbolAddress((void**)&p_fc1tb, g_fc1tb);
    cudaGetSymbolAddress((void**)&p_fc2tb, g_fc2tb);
    float* p_inc = (float*)p_XSb;  // XS dead after enc_scan; reuse as inc scratch

    const int SMEM_ENC = 57344 * 4;   // 229376 B
    const int SMEM_DEC = 53248 * 4;   // 212992 B
    const int SMEM_MLPB = 46598 * 4;  // 186392 B
    cudaFuncSetAttribute(enc_scan, cudaFuncAttributeMaxDynamicSharedMemorySize, SMEM_ENC);
    cudaFuncSetAttribute(dec_scan, cudaFuncAttributeMaxDynamicSharedMemorySize, SMEM_DEC);
    cudaFuncSetAttribute(mlp_batch, cudaFuncAttributeMaxDynamicSharedMemorySize, SMEM_MLPB);

    // R13 launch structure (separate prep + 128-thread conv) + R14's 512-thread mlp
    prep_all<<<480, 256>>>(enc_wih, enc_whh, dec_wih, dec_whh, fc1_w, fc2_w);             // 0
    conv_bn_kernel<<<BB, HD>>>(past, conv_w, conv_b, bn_gamma, bn_beta, bn_mean, bn_var, p_present);  // 1
    enc_scan<<<BB / 64, 512, SMEM_ENC>>>(p_wencih, p_wenchh, p_XSb, enc_bih, enc_bhh, p_hstateb);     // 2
    dec_scan<<<BB / 64, 512, SMEM_DEC>>>(p_wdecih, p_wdechh, p_hstateb, dec_bih, dec_bhh, p_hallb);   // 3 (profiled)
    mlp_batch<<<148, 512, SMEM_MLPB>>>((const __nv_bfloat16*)p_hallb, p_fc1tb, p_fc2tb,
                                       fc1_b, fc2_b, fc3_w, fc3_b, p_inc, NSTEPS * BB / 64);          // 4
    prefix_kernel<<<(BB * 6 + 255) / 256, 256>>>(p_inc, p_present, outp);                             // 5
}

// round 16
// speedup vs baseline: 1.0542x; 1.0230x over previous
#include <cuda_runtime.h>
#include <cuda_bf16.h>
#include <math.h>
#include <stdint.h>

#define BB 8192
#define TT 128
#define HD 128
#define GG 384
#define NSTEPS 30

typedef unsigned long long ull;

// ---------------- device scratch (static; no allocations allowed) ----------------
__device__ __nv_bfloat16 g_XSb[(size_t)TT * BB * HD];     // 256 MB; reused as fp32 inc later
__device__ __nv_bfloat16 g_hstateb[(size_t)BB * HD];      // encoder final state (bf16)
__device__ uint32_t g_hallb[(size_t)NSTEPS * BB * 64];    // decoder h per step (bf16x2)
__device__ float g_present[(size_t)BB * 6];
__device__ uint32_t g_wencih[24576];                      // ldsm-ready B fragment tiles
__device__ uint32_t g_wenchh[24576];
__device__ uint32_t g_wdecih[24576];
__device__ uint32_t g_wdechh[24576];
__device__ uint32_t g_fc1tb[16384];
__device__ uint32_t g_fc2tb[8192];

// ---------------- helpers ----------------
__device__ __forceinline__ uint32_t packbf(float x, float y) {
    __nv_bfloat162 v = __floats2bfloat162_rn(x, y);
    return *reinterpret_cast<uint32_t*>(&v);
}
__device__ __forceinline__ void mma16(float* d, const unsigned* a, unsigned b0, unsigned b1) {
    asm volatile(
        "mma.sync.aligned.m16n8k16.row.col.f32.bf16.bf16.f32 "
        "{%0,%1,%2,%3}, {%4,%5,%6,%7}, {%8,%9}, {%0,%1,%2,%3};"
        : "+f"(d[0]), "+f"(d[1]), "+f"(d[2]), "+f"(d[3])
        : "r"(a[0]), "r"(a[1]), "r"(a[2]), "r"(a[3]), "r"(b0), "r"(b1));
}
__device__ __forceinline__ unsigned s2u(const void* p) {
    return (unsigned)__cvta_generic_to_shared(p);
}
__device__ __forceinline__ void ldsm4(unsigned a[4], unsigned saddr) {
    asm volatile("ldmatrix.sync.aligned.m8n8.x4.shared.b16 {%0,%1,%2,%3}, [%4];"
                 : "=r"(a[0]), "=r"(a[1]), "=r"(a[2]), "=r"(a[3]) : "r"(saddr));
}
__device__ __forceinline__ float sigm(float x) {
    float t; asm("tanh.approx.f32 %0, %1;" : "=f"(t) : "f"(x * 0.5f));
    return fmaf(t, 0.5f, 0.5f);
}
__device__ __forceinline__ float tanha(float x) {
    float t; asm("tanh.approx.f32 %0, %1;" : "=f"(t) : "f"(x));
    return t;
}
__device__ __forceinline__ float2 ld2(const float* p) { return *reinterpret_cast<const float2*>(p); }
__device__ __forceinline__ void barg(int grp) {
    asm volatile("bar.sync %0, 256;" :: "r"(grp + 1) : "memory");
}
__device__ __forceinline__ void nsleep(unsigned ns) {
    asm volatile("nanosleep.u32 %0;" :: "r"(ns));
}

// cp.async
__device__ __forceinline__ void cpa16(void* smem, const void* g) {
    unsigned saddr = s2u(smem);
    asm volatile("cp.async.cg.shared.global [%0], [%1], 16;" :: "r"(saddr), "l"(g));
}
__device__ __forceinline__ void cp_commit() { asm volatile("cp.async.commit_group;"); }
template <int N> __device__ __forceinline__ void cp_wait() {
    asm volatile("cp.async.wait_group %0;" :: "n"(N));
}

// per-lane byte offset inside a 512B B-tile-pair block for ldsm.x4
__device__ __forceinline__ unsigned bpl(int lane) {
    return ((unsigned)(lane >> 3) << 7) | ((unsigned)(lane & 7) << 4);
}

// ---------------- prep: ldsm-pair B layout (standalone, 480 x 256) ----------------
__global__ void prep_all(const float* __restrict__ ewih, const float* __restrict__ ewhh,
                         const float* __restrict__ dwih, const float* __restrict__ dwhh,
                         const float* __restrict__ f1w, const float* __restrict__ f2w) {
    int b = blockIdx.x, tid = threadIdx.x;
    if (b < 384) {
        int wsel = b / 96;
        const float* src = (wsel == 0) ? ewih : (wsel == 1) ? ewhh : (wsel == 2) ? dwih : dwhh;
        uint32_t* dst = (wsel == 0) ? g_wencih : (wsel == 1) ? g_wenchh : (wsel == 2) ? g_wdecih : g_wdechh;
        int e = (b % 96) * 256 + tid;
        int n = e >> 6, k2 = e & 63;
        uint32_t v = packbf(src[n * HD + 2 * k2], src[n * HD + 2 * k2 + 1]);
        int pos = ((k2 >> 2) & 1) * 32 + ((n & 7) << 2) + (k2 & 3);
        dst[((k2 >> 3) * 48 + (n >> 3)) * 64 + pos] = v;
    } else if (b < 448) {
        int e = (b - 384) * 256 + tid;
        int n = e >> 6, k2 = e & 63;
        uint32_t v = packbf(f1w[n * 128 + 2 * k2], f1w[n * 128 + 2 * k2 + 1]);
        int pos = ((k2 >> 2) & 1) * 32 + ((n & 7) << 2) + (k2 & 3);
        g_fc1tb[((k2 >> 3) * 32 + (n >> 3)) * 64 + pos] = v;
    } else {
        int e = (b - 448) * 256 + tid;
        int n = e >> 7, k2 = e & 127;
        uint32_t v = packbf(f2w[n * 256 + 2 * k2], f2w[n * 256 + 2 * k2 + 1]);
        int pos = ((k2 >> 2) & 1) * 32 + ((n & 7) << 2) + (k2 & 3);
        g_fc2tb[((k2 >> 3) * 8 + (n >> 3)) * 64 + pos] = v;
    }
}

// conv1d(6->128,k=3,pad=1)+bias+relu+BN -> XS bf16 (smem-staged uint4 writes); present0
__global__ void conv_bn_kernel(const float* __restrict__ past, const float* __restrict__ cw,
                               const float* __restrict__ cb, const float* __restrict__ bng,
                               const float* __restrict__ bnb, const float* __restrict__ bnm,
                               const float* __restrict__ bnv, float* __restrict__ present) {
    __shared__ float p[6][TT];
    __shared__ __nv_bfloat16 stg[8][HD];
    int b = blockIdx.x, o = threadIdx.x;
    for (int i = o; i < 6 * TT; i += HD) p[i / TT][i % TT] = past[(size_t)b * 6 * TT + i];
    float w[6][3];
#pragma unroll
    for (int i = 0; i < 6; i++)
#pragma unroll
        for (int k = 0; k < 3; k++) w[i][k] = cw[(o * 6 + i) * 3 + k];
    float bias = cb[o];
    float scale = bng[0] * rsqrtf(bnv[0] + 1e-5f);
    float shift = bnb[0] - bnm[0] * scale;
    __syncthreads();
    for (int t0 = 0; t0 < TT; t0 += 8) {
#pragma unroll
        for (int t2 = 0; t2 < 8; t2++) {
            int t = t0 + t2;
            float acc = bias;
#pragma unroll
            for (int i = 0; i < 6; i++) {
                float l = (t > 0) ? p[i][t - 1] : 0.0f;
                float r = (t < TT - 1) ? p[i][t + 1] : 0.0f;
                acc += l * w[i][0] + p[i][t] * w[i][1] + r * w[i][2];
            }
            float v = fmaxf(acc, 0.0f) * scale + shift;
            stg[t2][o] = __float2bfloat16(v);
        }
        __syncthreads();
        {
            int tl = o >> 4, ch = o & 15;
            uint4 v4 = reinterpret_cast<const uint4*>(&stg[tl][0])[ch];
            reinterpret_cast<uint4*>(&g_XSb[((size_t)(t0 + tl) * BB + b) * HD])[ch] = v4;
        }
        __syncthreads();
    }
    if (o < 6) present[b * 6 + o] = p[o][TT - 1];
}

// ---------------- fused encoder scan: x-mma pipelined one step ahead ----------------
__global__ __launch_bounds__(512, 1) void enc_scan(const uint32_t* __restrict__ Wihg,
                                                   const uint32_t* __restrict__ Whhg,
                                                   const __nv_bfloat16* __restrict__ XS,
                                                   const float* __restrict__ bih,
                                                   const float* __restrict__ bhh,
                                                   __nv_bfloat16* __restrict__ hstate) {
    extern __shared__ uint32_t smu[];
    uint32_t* Wih = smu;            // 24576
    uint32_t* Whh = smu + 24576;    // 24576
    uint32_t* xs = smu + 49152;     // 4096 (64 rows x 64 u32, XOR-swizzled)
    uint32_t* hb = smu + 53248;     // 4096
    int tid = threadIdx.x;
    int lane = tid & 31, w = tid >> 5;
    int mw = w >> 3, nw = w & 7;
    int lq = lane >> 2, lr = lane & 3;
    int mat = lane >> 3, r8 = lane & 7;
    int m0 = blockIdx.x * 64;
    int gtid = tid & 255;

    for (int idx = tid; idx < 24576 / 4; idx += 512) {
        reinterpret_cast<uint4*>(Wih)[idx] = reinterpret_cast<const uint4*>(Wihg)[idx];
        reinterpret_cast<uint4*>(Whh)[idx] = reinterpret_cast<const uint4*>(Whhg)[idx];
    }
    for (int idx = tid; idx < 4096; idx += 512) hb[idx] = 0u;

    float brz[2][4], bihn[2][2], bhhn[2][2];
#pragma unroll
    for (int jj = 0; jj < 2; jj++) {
        int u = nw * 16 + jj * 8 + lr * 2;
        brz[jj][0] = bih[u] + bhh[u];
        brz[jj][1] = bih[u + 1] + bhh[u + 1];
        brz[jj][2] = bih[u + 128] + bhh[u + 128];
        brz[jj][3] = bih[u + 129] + bhh[u + 129];
        bihn[jj][0] = bih[u + 256]; bihn[jj][1] = bih[u + 257];
        bhhn[jj][0] = bhh[u + 256]; bhhn[jj][1] = bhh[u + 257];
    }

    int row0 = mw * 32 + (mat & 1) * 8 + r8;
    int row1 = row0 + 16;
    int rs = row0 & 7;
    int cm = mat >> 1;
    unsigned xs0 = s2u(xs) + row0 * 256, xs1 = s2u(xs) + row1 * 256;
    unsigned hbb0 = s2u(hb) + row0 * 256, hbb1 = s2u(hb) + row1 * 256;
    unsigned wbih = s2u(Wih) + bpl(lane);
    unsigned wbhh = s2u(Whh) + bpl(lane);

    int pfrow = mw * 32 + (gtid >> 3);
    int pfc = (gtid & 7) * 2;
    int prs = pfrow & 7;
    uint32_t* pfd0 = xs + pfrow * 64 + ((pfc ^ prs) << 2);
    uint32_t* pfd1 = xs + pfrow * 64 + (((pfc + 1) ^ prs) << 2);

    {   // x[0]
        const __nv_bfloat16* gsrc = XS + ((size_t)m0 + pfrow) * HD;
        cpa16(pfd0, gsrc + pfc * 8);
        cpa16(pfd1, gsrc + (pfc + 1) * 8);
        cp_commit();
        cp_wait<0>();
    }

    float hf[16];
#pragma unroll
    for (int i = 0; i < 16; i++) hf[i] = 0.0f;
    __syncthreads();
    if (mw == 1) nsleep(3000);

    float arz[2][4][4], axn[2][2][4], ahn[2][2][4];
#pragma unroll
    for (int i = 0; i < 2; i++) {
#pragma unroll
        for (int j = 0; j < 4; j++)
#pragma unroll
            for (int c = 0; c < 4; c++) arz[i][j][c] = 0.0f;
#pragma unroll
        for (int j = 0; j < 2; j++)
#pragma unroll
            for (int c = 0; c < 4; c++) { axn[i][j][c] = 0.0f; ahn[i][j][c] = 0.0f; }
    }

    // prologue: x-mma(0)
#pragma unroll
    for (int kc = 0; kc < 8; kc++) {
        unsigned sw = (unsigned)(((kc * 2 + cm) ^ rs) << 4);
        unsigned a0[4], a1[4];
        ldsm4(a0, xs0 + sw);
        ldsm4(a1, xs1 + sw);
#pragma unroll
        for (int g = 0; g < 3; g++) {
            int nt0 = g * 16 + nw * 2;
            unsigned b[4];
            ldsm4(b, wbih + (unsigned)((kc * 48 + nt0) * 256));
            float* d00 = (g < 2) ? arz[0][2 * g] : axn[0][0];
            float* d01 = (g < 2) ? arz[0][2 * g + 1] : axn[0][1];
            float* d10 = (g < 2) ? arz[1][2 * g] : axn[1][0];
            float* d11 = (g < 2) ? arz[1][2 * g + 1] : axn[1][1];
            mma16(d00, a0, b[0], b[1]);
            mma16(d01, a0, b[2], b[3]);
            mma16(d10, a1, b[0], b[1]);
            mma16(d11, a1, b[2], b[3]);
        }
    }
    barg(mw);

    for (int t = 0; t < TT; t++) {
        if (t + 1 < TT) {
            const __nv_bfloat16* gsrc = XS + ((size_t)(t + 1) * BB + m0 + pfrow) * HD;
            cpa16(pfd0, gsrc + pfc * 8);
            cpa16(pfd1, gsrc + (pfc + 1) * 8);
            cp_commit();
        }

        // h-mma(t)
#pragma unroll
        for (int kc = 0; kc < 8; kc++) {
            unsigned sw = (unsigned)(((kc * 2 + cm) ^ rs) << 4);
            unsigned a0[4], a1[4];
            ldsm4(a0, hbb0 + sw);
            ldsm4(a1, hbb1 + sw);
#pragma unroll
            for (int g = 0; g < 3; g++) {
                int nt0 = g * 16 + nw * 2;
                unsigned b[4];
                ldsm4(b, wbhh + (unsigned)((kc * 48 + nt0) * 256));
                float* d00 = (g < 2) ? arz[0][2 * g] : ahn[0][0];
                float* d01 = (g < 2) ? arz[0][2 * g + 1] : ahn[0][1];
                float* d10 = (g < 2) ? arz[1][2 * g] : ahn[1][0];
                float* d11 = (g < 2) ? arz[1][2 * g + 1] : ahn[1][1];
                mma16(d00, a0, b[0], b[1]);
                mma16(d01, a0, b[2], b[3]);
                mma16(d10, a1, b[0], b[1]);
                mma16(d11, a1, b[2], b[3]);
            }
        }
        barg(mw);

        // epilogue(t)
#pragma unroll
        for (int jj = 0; jj < 2; jj++) {
            int col = nw * 8 + jj * 4 + lr;
            int csw = col & 3;
            int cch = col >> 2;
#pragma unroll
            for (int i = 0; i < 2; i++) {
#pragma unroll
                for (int h8 = 0; h8 < 2; h8++) {
                    int lrow = mw * 32 + i * 16 + lq + h8 * 8;
                    int ci = h8 * 2;
                    float rx = sigm(arz[i][jj][ci] + brz[jj][0]);
                    float ry = sigm(arz[i][jj][ci + 1] + brz[jj][1]);
                    float zx = sigm(arz[i][jj + 2][ci] + brz[jj][2]);
                    float zy = sigm(arz[i][jj + 2][ci + 1] + brz[jj][3]);
                    float nx = tanha(axn[i][jj][ci] + bihn[jj][0] +
                                     rx * (ahn[i][jj][ci] + bhhn[jj][0]));
                    float ny = tanha(axn[i][jj][ci + 1] + bihn[jj][1] +
                                     ry * (ahn[i][jj][ci + 1] + bhhn[jj][1]));
                    int hx = ((jj * 2 + i) * 2 + h8) * 2;
                    float hxv = nx + zx * (hf[hx] - nx);
                    float hyv = ny + zy * (hf[hx + 1] - ny);
                    hf[hx] = hxv; hf[hx + 1] = hyv;
                    hb[lrow * 64 + ((cch ^ (lrow & 7)) << 2) + csw] = packbf(hxv, hyv);
                }
            }
        }

        if (t + 1 < TT) {
            cp_wait<0>();
#pragma unroll
            for (int i = 0; i < 2; i++) {
#pragma unroll
                for (int j = 0; j < 4; j++)
#pragma unroll
                    for (int c = 0; c < 4; c++) arz[i][j][c] = 0.0f;
#pragma unroll
                for (int j = 0; j < 2; j++)
#pragma unroll
                    for (int c = 0; c < 4; c++) { axn[i][j][c] = 0.0f; ahn[i][j][c] = 0.0f; }
            }
#pragma unroll
            for (int kc = 0; kc < 8; kc++) {
                unsigned sw = (unsigned)(((kc * 2 + cm) ^ rs) << 4);
                unsigned a0[4], a1[4];
                ldsm4(a0, xs0 + sw);
                ldsm4(a1, xs1 + sw);
#pragma unroll
                for (int g = 0; g < 3; g++) {
                    int nt0 = g * 16 + nw * 2;
                    unsigned b[4];
                    ldsm4(b, wbih + (unsigned)((kc * 48 + nt0) * 256));
                    float* d00 = (g < 2) ? arz[0][2 * g] : axn[0][0];
                    float* d01 = (g < 2) ? arz[0][2 * g + 1] : axn[0][1];
                    float* d10 = (g < 2) ? arz[1][2 * g] : axn[1][0];
                    float* d11 = (g < 2) ? arz[1][2 * g + 1] : axn[1][1];
                    mma16(d00, a0, b[0], b[1]);
                    mma16(d01, a0, b[2], b[3]);
                    mma16(d10, a1, b[0], b[1]);
                    mma16(d11, a1, b[2], b[3]);
                }
            }
        }
        barg(mw);
    }

    uint32_t* hsu = reinterpret_cast<uint32_t*>(hstate);
#pragma unroll
    for (int p = 0; p < 8; p++) {
        int idx = gtid + 256 * p;
        int row = mw * 32 + (idx >> 6), c = idx & 63;
        hsu[(size_t)(m0 + row) * 64 + c] = hb[row * 64 + (((c >> 2) ^ (row & 7)) << 2) + (c & 3)];
    }
}

// ---------------- fused decoder scan: step-0 x-mma(hstate@Wih), steps>=1 h-mma ------
__global__ __launch_bounds__(512, 1) void dec_scan(const uint32_t* __restrict__ Wihg,
                                                   const uint32_t* __restrict__ Whhg,
                                                   const __nv_bfloat16* __restrict__ hstate,
                                                   const float* __restrict__ bih,
                                                   const float* __restrict__ bhh,
                                                   uint32_t* __restrict__ hallb) {
    extern __shared__ uint32_t smu[];
    uint32_t* Wih = smu;            // 24576
    uint32_t* Whh = smu + 24576;    // 24576
    uint32_t* hb = smu + 49152;     // 4096
    int tid = threadIdx.x;
    int lane = tid & 31, w = tid >> 5;
    int mw = w >> 3, nw = w & 7;
    int lq = lane >> 2, lr = lane & 3;
    int mat = lane >> 3, r8 = lane & 7;
    int m0 = blockIdx.x * 64;
    int gtid = tid & 255;

    for (int idx = tid; idx < 24576 / 4; idx += 512) {
        reinterpret_cast<uint4*>(Wih)[idx] = reinterpret_cast<const uint4*>(Wihg)[idx];
        reinterpret_cast<uint4*>(Whh)[idx] = reinterpret_cast<const uint4*>(Whhg)[idx];
    }

    float brz[2][4], bihn[2][2], bhhn[2][2];
#pragma unroll
    for (int jj = 0; jj < 2; jj++) {
        int u = nw * 16 + jj * 8 + lr * 2;
        brz[jj][0] = bih[u] + bhh[u];
        brz[jj][1] = bih[u + 1] + bhh[u + 1];
        brz[jj][2] = bih[u + 128] + bhh[u + 128];
        brz[jj][3] = bih[u + 129] + bhh[u + 129];
        bihn[jj][0] = bih[u + 256]; bihn[jj][1] = bih[u + 257];
        bhhn[jj][0] = bhh[u + 256]; bhhn[jj][1] = bhh[u + 257];
    }

    int row0 = mw * 32 + (mat & 1) * 8 + r8;
    int row1 = row0 + 16;
    int rs = row0 & 7;
    int cm = mat >> 1;
    unsigned hbb0 = s2u(hb) + row0 * 256, hbb1 = s2u(hb) + row1 * 256;
    unsigned wbih = s2u(Wih) + bpl(lane);
    unsigned wbhh = s2u(Whh) + bpl(lane);

    {
        int pfrow = mw * 32 + (gtid >> 3);
        int pfc = (gtid & 7) * 2;
        int prs = pfrow & 7;
        const uint32_t* gsrc = reinterpret_cast<const uint32_t*>(hstate) + ((size_t)m0 + pfrow) * 64;
        cpa16(hb + pfrow * 64 + ((pfc ^ prs) << 2), gsrc + pfc * 4);
        cpa16(hb + pfrow * 64 + (((pfc + 1) ^ prs) << 2), gsrc + (pfc + 1) * 4);
        cp_commit();
        cp_wait<0>();
    }

    float hf[16];
#pragma unroll
    for (int i = 0; i < 16; i++) hf[i] = 0.0f;
    __syncthreads();

    for (int s = 0; s < NSTEPS; s++) {
        float arz[2][4][4], an[2][2][4];
#pragma unroll
        for (int i = 0; i < 2; i++) {
#pragma unroll
            for (int j = 0; j < 4; j++)
#pragma unroll
                for (int c = 0; c < 4; c++) arz[i][j][c] = 0.0f;
#pragma unroll
            for (int j = 0; j < 2; j++)
#pragma unroll
                for (int c = 0; c < 4; c++) an[i][j][c] = 0.0f;
        }
        unsigned wb = (s == 0) ? wbih : wbhh;
#pragma unroll
        for (int kc = 0; kc < 8; kc++) {
            unsigned sw = (unsigned)(((kc * 2 + cm) ^ rs) << 4);
            unsigned a0[4], a1[4];
            ldsm4(a0, hbb0 + sw);
            ldsm4(a1, hbb1 + sw);
#pragma unroll
            for (int g = 0; g < 3; g++) {
                int nt0 = g * 16 + nw * 2;
                unsigned b[4];
                ldsm4(b, wb + (unsigned)((kc * 48 + nt0) * 256));
                float* d00 = (g < 2) ? arz[0][2 * g] : an[0][0];
                float* d01 = (g < 2) ? arz[0][2 * g + 1] : an[0][1];
                float* d10 = (g < 2) ? arz[1][2 * g] : an[1][0];
                float* d11 = (g < 2) ? arz[1][2 * g + 1] : an[1][1];
                mma16(d00, a0, b[0], b[1]);
                mma16(d01, a0, b[2], b[3]);
                mma16(d10, a1, b[0], b[1]);
                mma16(d11, a1, b[2], b[3]);
            }
        }
        barg(mw);

#pragma unroll
        for (int jj = 0; jj < 2; jj++) {
            int col = nw * 8 + jj * 4 + lr;
            int csw = col & 3;
            int cch = col >> 2;
#pragma unroll
            for (int i = 0; i < 2; i++) {
#pragma unroll
                for (int h8 = 0; h8 < 2; h8++) {
                    int lrow = mw * 32 + i * 16 + lq + h8 * 8;
                    int ci = h8 * 2;
                    float rx = sigm(arz[i][jj][ci] + brz[jj][0]);
                    float ry = sigm(arz[i][jj][ci + 1] + brz[jj][1]);
                    float zx = sigm(arz[i][jj + 2][ci] + brz[jj][2]);
                    float zy = sigm(arz[i][jj + 2][ci + 1] + brz[jj][3]);
                    float nx, ny;
                    if (s == 0) {
                        nx = tanha(an[i][jj][ci] + bihn[jj][0] + rx * bhhn[jj][0]);
                        ny = tanha(an[i][jj][ci + 1] + bihn[jj][1] + ry * bhhn[jj][1]);
                    } else {
                        nx = tanha(bihn[jj][0] + rx * (an[i][jj][ci] + bhhn[jj][0]));
                        ny = tanha(bihn[jj][1] + ry * (an[i][jj][ci + 1] + bhhn[jj][1]));
                    }
                    int hx = ((jj * 2 + i) * 2 + h8) * 2;
                    float hxv = nx + zx * (hf[hx] - nx);
                    float hyv = ny + zy * (hf[hx + 1] - ny);
                    hf[hx] = hxv; hf[hx + 1] = hyv;
                    hb[lrow * 64 + ((cch ^ (lrow & 7)) << 2) + csw] = packbf(hxv, hyv);
                }
            }
        }
        barg(mw);

        uint32_t* dst = hallb + ((size_t)s * BB + m0) * 64;
#pragma unroll
        for (int p = 0; p < 8; p++) {
            int idx = gtid + 256 * p;
            int row = mw * 32 + (idx >> 6), c = idx & 63;
            dst[row * 64 + c] = hb[row * 64 + (((c >> 2) ^ (row & 7)) << 2) + (c & 3)];
        }
    }
}

// ---------------- batched MLP (256 threads, R13 measured-best config) ---------------
__global__ __launch_bounds__(256, 1) void mlp_batch(
    const __nv_bfloat16* __restrict__ hall,
    const uint32_t* __restrict__ F1g, const uint32_t* __restrict__ F2g,
    const float* __restrict__ fc1b, const float* __restrict__ fc2b,
    const float* __restrict__ fc3w, const float* __restrict__ fc3b,
    float* __restrict__ inc, int ntiles) {
    extern __shared__ uint32_t smu[];
    uint32_t* F1 = smu;                  // 16384
    uint32_t* F2 = smu + 16384;          // 8192
    uint32_t* As = smu + 24576;          // 2 x 64*68
    uint32_t* A1 = smu + 33280;          // 64*132
    float* A2T = (float*)(smu + 41728);  // 65*64
    float* B1 = (float*)(smu + 45888);
    float* B2 = (float*)(smu + 46144);
    float* B3W = (float*)(smu + 46208);
    float* B3 = (float*)(smu + 46592);   // end 46598 u32 = 186392 B

    int tid = threadIdx.x;
    int lane = tid & 31, w = tid >> 5;
    int mw = w >> 2, nw = w & 3, lq = lane >> 2, lr = lane & 3;
    int mat = lane >> 3, r8 = lane & 7;

    for (int i = tid; i < 16384; i += 256) F1[i] = F1g[i];
    for (int i = tid; i < 8192; i += 256) F2[i] = F2g[i];
    if (tid < 256) B1[tid] = fc1b[tid];
    if (tid < 64) B2[tid] = fc2b[tid];
    if (tid < 6) B3[tid] = fc3b[tid];
    for (int i = tid; i < 384; i += 256) B3W[i] = fc3w[i];

    unsigned asb = s2u(As + (mw * 32 + (mat & 1) * 8 + r8) * 68 + (mat >> 1) * 4);
    unsigned a1b0 = s2u(A1 + (mw * 32 + (mat & 1) * 8 + r8) * 132 + (mat >> 1) * 4);
    unsigned a1b1 = a1b0 + 16 * 132 * 4;
    unsigned f1b = s2u(F1) + bpl(lane);
    unsigned f2b = s2u(F2) + bpl(lane);

    int grid = gridDim.x;
    int tile0 = blockIdx.x;
    if (tile0 < ntiles) {
#pragma unroll
        for (int j = 0; j < 4; j++) {
            int idx = tid + 256 * j, row = idx >> 4, c = idx & 15;
            cpa16(As + row * 68 + c * 4, hall + ((size_t)tile0 * 64 + row) * HD + c * 8);
        }
        cp_commit();
    }
    __syncthreads();

    int it = 0;
    for (int tile = tile0; tile < ntiles; tile += grid, it++) {
        int nxt = tile + grid;
        if (nxt < ntiles) {
            uint32_t* xb = As + ((it + 1) & 1) * 4352;
#pragma unroll
            for (int j = 0; j < 4; j++) {
                int idx = tid + 256 * j, row = idx >> 4, c = idx & 15;
                cpa16(xb + row * 68 + c * 4, hall + ((size_t)nxt * 64 + row) * HD + c * 8);
            }
            cp_commit();
            cp_wait<1>();
        } else {
            cp_wait<0>();
        }
        __syncthreads();  // cur tile visible; A1/A2T free

        unsigned ab0 = asb + (unsigned)((it & 1) * 4352 * 4);
        unsigned ab1 = ab0 + 16 * 68 * 4;

        // fc1: 64 x 256 = relu(h @ fc1^T + b1) -> A1 (bf16)
        float acc1[2][8][4];
#pragma unroll
        for (int i = 0; i < 2; i++)
#pragma unroll
            for (int j = 0; j < 8; j++)
#pragma unroll
                for (int c = 0; c < 4; c++) acc1[i][j][c] = 0.0f;
#pragma unroll
        for (int kc = 0; kc < 8; kc++) {
            unsigned a0[4], a1r[4];
            ldsm4(a0, ab0 + kc * 32);
            ldsm4(a1r, ab1 + kc * 32);
#pragma unroll
            for (int p = 0; p < 4; p++) {
                int nt0 = nw * 8 + 2 * p;
                unsigned b[4];
                ldsm4(b, f1b + (unsigned)((kc * 32 + nt0) * 256));
                mma16(acc1[0][2 * p], a0, b[0], b[1]);
                mma16(acc1[0][2 * p + 1], a0, b[2], b[3]);
                mma16(acc1[1][2 * p], a1r, b[0], b[1]);
                mma16(acc1[1][2 * p + 1], a1r, b[2], b[3]);
            }
        }
#pragma unroll
        for (int j2 = 0; j2 < 8; j2++) {
            int col = nw * 64 + j2 * 8 + lr * 2;
            float2 bb = ld2(B1 + col);
#pragma unroll
            for (int i = 0; i < 2; i++) {
                int row = mw * 32 + i * 16 + lq;
                A1[row * 132 + (col >> 1)] =
                    packbf(fmaxf(acc1[i][j2][0] + bb.x, 0.0f), fmaxf(acc1[i][j2][1] + bb.y, 0.0f));
                A1[(row + 8) * 132 + (col >> 1)] =
                    packbf(fmaxf(acc1[i][j2][2] + bb.x, 0.0f), fmaxf(acc1[i][j2][3] + bb.y, 0.0f));
            }
        }
        __syncthreads();

        // fc2: 64 x 64 = A1 @ fc2^T + b2 -> A2T (fp32, transposed)
        float acc2[2][2][4];
#pragma unroll
        for (int i = 0; i < 2; i++)
#pragma unroll
            for (int j = 0; j < 2; j++)
#pragma unroll
                for (int c = 0; c < 4; c++) acc2[i][j][c] = 0.0f;
#pragma unroll
        for (int kc = 0; kc < 16; kc++) {
            unsigned a0[4], a1r[4];
            ldsm4(a0, a1b0 + kc * 32);
            ldsm4(a1r, a1b1 + kc * 32);
            unsigned b[4];
            ldsm4(b, f2b + (unsigned)((kc * 8 + nw * 2) * 256));
            mma16(acc2[0][0], a0, b[0], b[1]);
            mma16(acc2[0][1], a0, b[2], b[3]);
            mma16(acc2[1][0], a1r, b[0], b[1]);
            mma16(acc2[1][1], a1r, b[2], b[3]);
        }
#pragma unroll
        for (int j2 = 0; j2 < 2; j2++) {
            int col = nw * 16 + j2 * 8 + lr * 2;
            float2 bb = ld2(B2 + col);
#pragma unroll
            for (int i = 0; i < 2; i++) {
                int row = mw * 32 + i * 16 + lq;
                A2T[col * 65 + row] = acc2[i][j2][0] + bb.x;
                A2T[(col + 1) * 65 + row] = acc2[i][j2][1] + bb.y;
                A2T[col * 65 + row + 8] = acc2[i][j2][2] + bb.x;
                A2T[(col + 1) * 65 + row + 8] = acc2[i][j2][3] + bb.y;
            }
        }
        __syncthreads();

        // fc3 (fp32): inc[tile*64 + r][c], contiguous 384-float region per tile
#pragma unroll
        for (int p = 0; p < 2; p++) {
            int li = tid + 256 * p;
            if (li < 384) {
                int r = li & 63, c = li >> 6;
                float acc = B3[c];
#pragma unroll
                for (int k = 0; k < 64; k++) acc = fmaf(A2T[k * 65 + r], B3W[c * 64 + k], acc);
                inc[(size_t)(tile * 64 + r) * 6 + c] = acc;
            }
        }
        __syncthreads();  // A2T/A1 free for next tile
    }
}

// present prefix-accumulation + final output (same fp32 order as the old scan)
__global__ void prefix_kernel(const float* __restrict__ inc,
                              const float* __restrict__ present0,
                              float* __restrict__ outp) {
    int i = blockIdx.x * 256 + threadIdx.x;
    if (i < BB * 6) {
        int b = i / 6, c = i % 6;
        float pres = present0[i];
#pragma unroll
        for (int s = 0; s < NSTEPS; s++) {
            pres += inc[((size_t)s * BB + b) * 6 + c];
            outp[(size_t)b * 180 + c * 30 + s] = pres;
        }
    }
}

// ---------------- host ----------------
extern "C" void kernel_launch(void* const* d_in, const int* in_sizes, int n_in,
                              void* d_out, int out_size) {
    const float* past = (const float*)d_in[0];
    const float* conv_w = (const float*)d_in[1];
    const float* conv_b = (const float*)d_in[2];
    const float* bn_gamma = (const float*)d_in[3];
    const float* bn_beta = (const float*)d_in[4];
    const float* bn_mean = (const float*)d_in[5];
    const float* bn_var = (const float*)d_in[6];
    const float* enc_wih = (const float*)d_in[7];
    const float* enc_whh = (const float*)d_in[8];
    const float* enc_bih = (const float*)d_in[9];
    const float* enc_bhh = (const float*)d_in[10];
    const float* dec_wih = (const float*)d_in[11];
    const float* dec_whh = (const float*)d_in[12];
    const float* dec_bih = (const float*)d_in[13];
    const float* dec_bhh = (const float*)d_in[14];
    const float* fc1_w = (const float*)d_in[15];
    const float* fc1_b = (const float*)d_in[16];
    const float* fc2_w = (const float*)d_in[17];
    const float* fc2_b = (const float*)d_in[18];
    const float* fc3_w = (const float*)d_in[19];
    const float* fc3_b = (const float*)d_in[20];
    float* outp = (float*)d_out;

    __nv_bfloat16 *p_XSb, *p_hstateb;
    uint32_t *p_hallb, *p_wencih, *p_wenchh, *p_wdecih, *p_wdechh, *p_fc1tb, *p_fc2tb;
    float* p_present;
    cudaGetSymbolAddress((void**)&p_XSb, g_XSb);
    cudaGetSymbolAddress((void**)&p_hstateb, g_hstateb);
    cudaGetSymbolAddress((void**)&p_hallb, g_hallb);
    cudaGetSymbolAddress((void**)&p_present, g_present);
    cudaGetSymbolAddress((void**)&p_wencih, g_wencih);
    cudaGetSymbolAddress((void**)&p_wenchh, g_wenchh);
    cudaGetSymbolAddress((void**)&p_wdecih, g_wdecih);
    cudaGetSymbolAddress((void**)&p_wdechh, g_wdechh);
    cudaGetSymbolAddress((void**)&p_fc1tb, g_fc1tb);
    cudaGetSymbolAddress((void**)&p_fc2tb, g_fc2tb);
    float* p_inc = (float*)p_XSb;  // XS dead after enc_scan; reuse as inc scratch

    const int SMEM_ENC = 57344 * 4;   // 229376 B
    const int SMEM_DEC = 53248 * 4;   // 212992 B
    const int SMEM_MLPB = 46598 * 4;  // 186392 B
    cudaFuncSetAttribute(enc_scan, cudaFuncAttributeMaxDynamicSharedMemorySize, SMEM_ENC);
    cudaFuncSetAttribute(dec_scan, cudaFuncAttributeMaxDynamicSharedMemorySize, SMEM_DEC);
    cudaFuncSetAttribute(mlp_batch, cudaFuncAttributeMaxDynamicSharedMemorySize, SMEM_MLPB);

    // R13 measured-best configuration (955us), dec nsleep removed
    prep_all<<<480, 256>>>(enc_wih, enc_whh, dec_wih, dec_whh, fc1_w, fc2_w);             // 0
    conv_bn_kernel<<<BB, HD>>>(past, conv_w, conv_b, bn_gamma, bn_beta, bn_mean, bn_var, p_present);  // 1
    enc_scan<<<BB / 64, 512, SMEM_ENC>>>(p_wencih, p_wenchh, p_XSb, enc_bih, enc_bhh, p_hstateb);     // 2
    dec_scan<<<BB / 64, 512, SMEM_DEC>>>(p_wdecih, p_wdechh, p_hstateb, dec_bih, dec_bhh, p_hallb);   // 3 (profiled)
    mlp_batch<<<148, 256, SMEM_MLPB>>>((const __nv_bfloat16*)p_hallb, p_fc1tb, p_fc2tb,
                                       fc1_b, fc2_b, fc3_w, fc3_b, p_inc, NSTEPS * BB / 64);          // 4
    prefix_kernel<<<(BB * 6 + 255) / 256, 256>>>(p_inc, p_present, outp);                             // 5
}

// round 17
// speedup vs baseline: 1.1090x; 1.0520x over previous
#include <cuda_runtime.h>
#include <cuda_bf16.h>
#include <math.h>
#include <stdint.h>

#define BB 8192
#define TT 128
#define HD 128
#define GG 384
#define NSTEPS 30

typedef unsigned long long ull;

// ---------------- device scratch (static; no allocations allowed) ----------------
__device__ __nv_bfloat16 g_XSb[(size_t)TT * BB * HD];     // 256 MB; reused as fp32 inc later
__device__ __nv_bfloat16 g_hstateb[(size_t)BB * HD];      // encoder final state (bf16)
__device__ uint32_t g_hallb[(size_t)NSTEPS * BB * 64];    // decoder h per step (bf16x2)
__device__ float g_present[(size_t)BB * 6];
__device__ uint32_t g_wencih[24576];                      // ldsm-ready B fragment tiles
__device__ uint32_t g_wenchh[24576];
__device__ uint32_t g_wdecih[24576];
__device__ uint32_t g_wdechh[24576];
__device__ uint32_t g_fc1tb[16384];
__device__ uint32_t g_fc2tb[8192];
__device__ uint32_t g_wconv[2048];                        // conv W tiles (2 kc x 16 nt)

// ---------------- helpers ----------------
__device__ __forceinline__ uint32_t packbf(float x, float y) {
    __nv_bfloat162 v = __floats2bfloat162_rn(x, y);
    return *reinterpret_cast<uint32_t*>(&v);
}
__device__ __forceinline__ void mma16(float* d, const unsigned* a, unsigned b0, unsigned b1) {
    asm volatile(
        "mma.sync.aligned.m16n8k16.row.col.f32.bf16.bf16.f32 "
        "{%0,%1,%2,%3}, {%4,%5,%6,%7}, {%8,%9}, {%0,%1,%2,%3};"
        : "+f"(d[0]), "+f"(d[1]), "+f"(d[2]), "+f"(d[3])
        : "r"(a[0]), "r"(a[1]), "r"(a[2]), "r"(a[3]), "r"(b0), "r"(b1));
}
__device__ __forceinline__ unsigned s2u(const void* p) {
    return (unsigned)__cvta_generic_to_shared(p);
}
__device__ __forceinline__ void ldsm4(unsigned a[4], unsigned saddr) {
    asm volatile("ldmatrix.sync.aligned.m8n8.x4.shared.b16 {%0,%1,%2,%3}, [%4];"
                 : "=r"(a[0]), "=r"(a[1]), "=r"(a[2]), "=r"(a[3]) : "r"(saddr));
}
__device__ __forceinline__ float sigm(float x) {
    float t; asm("tanh.approx.f32 %0, %1;" : "=f"(t) : "f"(x * 0.5f));
    return fmaf(t, 0.5f, 0.5f);
}
__device__ __forceinline__ float tanha(float x) {
    float t; asm("tanh.approx.f32 %0, %1;" : "=f"(t) : "f"(x));
    return t;
}
__device__ __forceinline__ float2 ld2(const float* p) { return *reinterpret_cast<const float2*>(p); }
__device__ __forceinline__ void barg(int grp) {
    asm volatile("bar.sync %0, 256;" :: "r"(grp + 1) : "memory");
}
__device__ __forceinline__ void nsleep(unsigned ns) {
    asm volatile("nanosleep.u32 %0;" :: "r"(ns));
}

// cp.async
__device__ __forceinline__ void cpa16(void* smem, const void* g) {
    unsigned saddr = s2u(smem);
    asm volatile("cp.async.cg.shared.global [%0], [%1], 16;" :: "r"(saddr), "l"(g));
}
__device__ __forceinline__ void cp_commit() { asm volatile("cp.async.commit_group;"); }
template <int N> __device__ __forceinline__ void cp_wait() {
    asm volatile("cp.async.wait_group %0;" :: "n"(N));
}

// per-lane byte offset inside a 512B B-tile-pair block for ldsm.x4
__device__ __forceinline__ unsigned bpl(int lane) {
    return ((unsigned)(lane >> 3) << 7) | ((unsigned)(lane & 7) << 4);
}

// ---------------- prep: ldsm-pair B layouts (488 x 256) ----------------
__global__ void prep_all(const float* __restrict__ ewih, const float* __restrict__ ewhh,
                         const float* __restrict__ dwih, const float* __restrict__ dwhh,
                         const float* __restrict__ f1w, const float* __restrict__ f2w,
                         const float* __restrict__ cw) {
    int b = blockIdx.x, tid = threadIdx.x;
    if (b < 384) {
        int wsel = b / 96;
        const float* src = (wsel == 0) ? ewih : (wsel == 1) ? ewhh : (wsel == 2) ? dwih : dwhh;
        uint32_t* dst = (wsel == 0) ? g_wencih : (wsel == 1) ? g_wenchh : (wsel == 2) ? g_wdecih : g_wdechh;
        int e = (b % 96) * 256 + tid;
        int n = e >> 6, k2 = e & 63;
        uint32_t v = packbf(src[n * HD + 2 * k2], src[n * HD + 2 * k2 + 1]);
        int pos = ((k2 >> 2) & 1) * 32 + ((n & 7) << 2) + (k2 & 3);
        dst[((k2 >> 3) * 48 + (n >> 3)) * 64 + pos] = v;
    } else if (b < 448) {
        int e = (b - 384) * 256 + tid;
        int n = e >> 6, k2 = e & 63;
        uint32_t v = packbf(f1w[n * 128 + 2 * k2], f1w[n * 128 + 2 * k2 + 1]);
        int pos = ((k2 >> 2) & 1) * 32 + ((n & 7) << 2) + (k2 & 3);
        g_fc1tb[((k2 >> 3) * 32 + (n >> 3)) * 64 + pos] = v;
    } else if (b < 480) {
        int e = (b - 448) * 256 + tid;
        int n = e >> 7, k2 = e & 127;
        uint32_t v = packbf(f2w[n * 256 + 2 * k2], f2w[n * 256 + 2 * k2 + 1]);
        int pos = ((k2 >> 2) & 1) * 32 + ((n & 7) << 2) + (k2 & 3);
        g_fc2tb[((k2 >> 3) * 8 + (n >> 3)) * 64 + pos] = v;
    } else {
        // conv weights: n = out channel (128), K = 18 (i*3+k) padded to 32
        int e = (b - 480) * 256 + tid;      // 0..2047
        int n = e >> 4, k2 = e & 15;
        int kk0 = 2 * k2, kk1 = 2 * k2 + 1;
        float v0 = (kk0 < 18) ? cw[(n * 6 + kk0 / 3) * 3 + kk0 % 3] : 0.0f;
        float v1 = (kk1 < 18) ? cw[(n * 6 + kk1 / 3) * 3 + kk1 % 3] : 0.0f;
        int pos = ((k2 >> 2) & 1) * 32 + ((n & 7) << 2) + (k2 & 3);
        g_wconv[((k2 >> 3) * 16 + (n >> 3)) * 64 + pos] = packbf(v0, v1);
    }
}

// ---------------- conv as bf16 mma GEMM: y = relu(A[64t x 18] @ Wc^T + cb)*scale+shift
// one block per batch row; 2 t-tiles of 64
__global__ __launch_bounds__(256) void conv_mma_kernel(
    const float* __restrict__ past, const uint32_t* __restrict__ Wcg,
    const float* __restrict__ cb, const float* __restrict__ bng,
    const float* __restrict__ bnb, const float* __restrict__ bnm,
    const float* __restrict__ bnv, float* __restrict__ present) {
    __shared__ float pastS[6][TT];     // 3072 B
    __shared__ uint32_t Wc[2048];      // 8 KB
    __shared__ uint32_t As[64 * 20];   // 5120 B (rows stride 80B -> ldsm conflict-free)
    __shared__ uint32_t stg[64 * 64];  // 16 KB output staging
    __shared__ float cbS[128];
    int b = blockIdx.x, tid = threadIdx.x;
    int lane = tid & 31, w = tid >> 5;
    int mw = w >> 2, nw = w & 3, lq = lane >> 2, lr = lane & 3;
    int mat = lane >> 3, r8 = lane & 7;

    for (int i = tid; i < 6 * TT; i += 256) pastS[i / TT][i % TT] = past[(size_t)b * 6 * TT + i];
    for (int i = tid; i < 2048; i += 256) Wc[i] = Wcg[i];
    if (tid < 128) cbS[tid] = cb[tid];
    for (int i = tid; i < 64 * 20; i += 256) As[i] = 0u;   // zero K-pad once
    float scale = bng[0] * rsqrtf(bnv[0] + 1e-5f);
    float shift = bnb[0] - bnm[0] * scale;
    __syncthreads();
    if (tid < 6) present[b * 6 + tid] = pastS[tid][TT - 1];

    unsigned wcb = s2u(Wc) + bpl(lane);
    unsigned ab = s2u(As) + (mw * 32 + (mat & 1) * 8 + r8) * 80 + (mat >> 1) * 16;

#pragma unroll
    for (int tile = 0; tile < 2; tile++) {
        int t0 = tile * 64;
        // build A: rows=local t, K entries kk<18 (e=0..8 u32 pairs)
        for (int idx = tid; idx < 64 * 9; idx += 256) {
            int row = idx / 9, e = idx % 9;
            int kk0 = 2 * e, kk1 = 2 * e + 1;
            float v0 = 0.0f, v1 = 0.0f;
            {
                int tg = t0 + row + (kk0 % 3) - 1;
                if (tg >= 0 && tg < TT) v0 = pastS[kk0 / 3][tg];
            }
            {
                int tg = t0 + row + (kk1 % 3) - 1;
                if (tg >= 0 && tg < TT) v1 = pastS[kk1 / 3][tg];
            }
            As[row * 20 + e] = packbf(v0, v1);
        }
        __syncthreads();

        float acc[2][4][4];
#pragma unroll
        for (int i = 0; i < 2; i++)
#pragma unroll
            for (int j = 0; j < 4; j++)
#pragma unroll
                for (int c = 0; c < 4; c++) acc[i][j][c] = 0.0f;
#pragma unroll
        for (int kc = 0; kc < 2; kc++) {
            unsigned a0[4], a1[4];
            ldsm4(a0, ab + kc * 32);
            ldsm4(a1, ab + 16 * 80 + kc * 32);
#pragma unroll
            for (int p = 0; p < 2; p++) {
                int nt0 = nw * 4 + 2 * p;
                unsigned bb[4];
                ldsm4(bb, wcb + (unsigned)((kc * 16 + nt0) * 256));
                mma16(acc[0][2 * p], a0, bb[0], bb[1]);
                mma16(acc[0][2 * p + 1], a0, bb[2], bb[3]);
                mma16(acc[1][2 * p], a1, bb[0], bb[1]);
                mma16(acc[1][2 * p + 1], a1, bb[2], bb[3]);
            }
        }

        // epilogue: relu + BN -> stg (bf16x2)
#pragma unroll
        for (int j = 0; j < 4; j++) {
            int col = nw * 32 + j * 8 + lr * 2;
            float c0 = cbS[col], c1 = cbS[col + 1];
#pragma unroll
            for (int i = 0; i < 2; i++) {
                int row = mw * 32 + i * 16 + lq;
                float x0 = fmaxf(acc[i][j][0] + c0, 0.0f) * scale + shift;
                float y0 = fmaxf(acc[i][j][1] + c1, 0.0f) * scale + shift;
                float x1 = fmaxf(acc[i][j][2] + c0, 0.0f) * scale + shift;
                float y1 = fmaxf(acc[i][j][3] + c1, 0.0f) * scale + shift;
                stg[row * 64 + (col >> 1)] = packbf(x0, y0);
                stg[(row + 8) * 64 + (col >> 1)] = packbf(x1, y1);
            }
        }
        __syncthreads();  // stg complete; all mma reads of As done

        for (int idx = tid; idx < 64 * 16; idx += 256) {
            int row = idx >> 4, ch = idx & 15;
            uint4 v = reinterpret_cast<const uint4*>(stg + row * 64)[ch];
            reinterpret_cast<uint4*>(&g_XSb[((size_t)(t0 + row) * BB + b) * HD])[ch] = v;
        }
        __syncthreads();  // stg free; As rebuildable
    }
}

// ---------------- fused encoder scan: x-mma pipelined one step ahead ----------------
__global__ __launch_bounds__(512, 1) void enc_scan(const uint32_t* __restrict__ Wihg,
                                                   const uint32_t* __restrict__ Whhg,
                                                   const __nv_bfloat16* __restrict__ XS,
                                                   const float* __restrict__ bih,
                                                   const float* __restrict__ bhh,
                                                   __nv_bfloat16* __restrict__ hstate) {
    extern __shared__ uint32_t smu[];
    uint32_t* Wih = smu;            // 24576
    uint32_t* Whh = smu + 24576;    // 24576
    uint32_t* xs = smu + 49152;     // 4096 (64 rows x 64 u32, XOR-swizzled)
    uint32_t* hb = smu + 53248;     // 4096
    int tid = threadIdx.x;
    int lane = tid & 31, w = tid >> 5;
    int mw = w >> 3, nw = w & 7;
    int lq = lane >> 2, lr = lane & 3;
    int mat = lane >> 3, r8 = lane & 7;
    int m0 = blockIdx.x * 64;
    int gtid = tid & 255;

    for (int idx = tid; idx < 24576 / 4; idx += 512) {
        reinterpret_cast<uint4*>(Wih)[idx] = reinterpret_cast<const uint4*>(Wihg)[idx];
        reinterpret_cast<uint4*>(Whh)[idx] = reinterpret_cast<const uint4*>(Whhg)[idx];
    }
    for (int idx = tid; idx < 4096; idx += 512) hb[idx] = 0u;

    float brz[2][4], bihn[2][2], bhhn[2][2];
#pragma unroll
    for (int jj = 0; jj < 2; jj++) {
        int u = nw * 16 + jj * 8 + lr * 2;
        brz[jj][0] = bih[u] + bhh[u];
        brz[jj][1] = bih[u + 1] + bhh[u + 1];
        brz[jj][2] = bih[u + 128] + bhh[u + 128];
        brz[jj][3] = bih[u + 129] + bhh[u + 129];
        bihn[jj][0] = bih[u + 256]; bihn[jj][1] = bih[u + 257];
        bhhn[jj][0] = bhh[u + 256]; bhhn[jj][1] = bhh[u + 257];
    }

    int row0 = mw * 32 + (mat & 1) * 8 + r8;
    int row1 = row0 + 16;
    int rs = row0 & 7;
    int cm = mat >> 1;
    unsigned xs0 = s2u(xs) + row0 * 256, xs1 = s2u(xs) + row1 * 256;
    unsigned hbb0 = s2u(hb) + row0 * 256, hbb1 = s2u(hb) + row1 * 256;
    unsigned wbih = s2u(Wih) + bpl(lane);
    unsigned wbhh = s2u(Whh) + bpl(lane);

    int pfrow = mw * 32 + (gtid >> 3);
    int pfc = (gtid & 7) * 2;
    int prs = pfrow & 7;
    uint32_t* pfd0 = xs + pfrow * 64 + ((pfc ^ prs) << 2);
    uint32_t* pfd1 = xs + pfrow * 64 + (((pfc + 1) ^ prs) << 2);

    {   // x[0]
        const __nv_bfloat16* gsrc = XS + ((size_t)m0 + pfrow) * HD;
        cpa16(pfd0, gsrc + pfc * 8);
        cpa16(pfd1, gsrc + (pfc + 1) * 8);
        cp_commit();
        cp_wait<0>();
    }

    float hf[16];
#pragma unroll
    for (int i = 0; i < 16; i++) hf[i] = 0.0f;
    __syncthreads();
    if (mw == 1) nsleep(3000);

    float arz[2][4][4], axn[2][2][4], ahn[2][2][4];
#pragma unroll
    for (int i = 0; i < 2; i++) {
#pragma unroll
        for (int j = 0; j < 4; j++)
#pragma unroll
            for (int c = 0; c < 4; c++) arz[i][j][c] = 0.0f;
#pragma unroll
        for (int j = 0; j < 2; j++)
#pragma unroll
            for (int c = 0; c < 4; c++) { axn[i][j][c] = 0.0f; ahn[i][j][c] = 0.0f; }
    }

    // prologue: x-mma(0)
#pragma unroll
    for (int kc = 0; kc < 8; kc++) {
        unsigned sw = (unsigned)(((kc * 2 + cm) ^ rs) << 4);
        unsigned a0[4], a1[4];
        ldsm4(a0, xs0 + sw);
        ldsm4(a1, xs1 + sw);
#pragma unroll
        for (int g = 0; g < 3; g++) {
            int nt0 = g * 16 + nw * 2;
            unsigned b[4];
            ldsm4(b, wbih + (unsigned)((kc * 48 + nt0) * 256));
            float* d00 = (g < 2) ? arz[0][2 * g] : axn[0][0];
            float* d01 = (g < 2) ? arz[0][2 * g + 1] : axn[0][1];
            float* d10 = (g < 2) ? arz[1][2 * g] : axn[1][0];
            float* d11 = (g < 2) ? arz[1][2 * g + 1] : axn[1][1];
            mma16(d00, a0, b[0], b[1]);
            mma16(d01, a0, b[2], b[3]);
            mma16(d10, a1, b[0], b[1]);
            mma16(d11, a1, b[2], b[3]);
        }
    }
    barg(mw);

    for (int t = 0; t < TT; t++) {
        if (t + 1 < TT) {
            const __nv_bfloat16* gsrc = XS + ((size_t)(t + 1) * BB + m0 + pfrow) * HD;
            cpa16(pfd0, gsrc + pfc * 8);
            cpa16(pfd1, gsrc + (pfc + 1) * 8);
            cp_commit();
        }

        // h-mma(t)
#pragma unroll
        for (int kc = 0; kc < 8; kc++) {
            unsigned sw = (unsigned)(((kc * 2 + cm) ^ rs) << 4);
            unsigned a0[4], a1[4];
            ldsm4(a0, hbb0 + sw);
            ldsm4(a1, hbb1 + sw);
#pragma unroll
            for (int g = 0; g < 3; g++) {
                int nt0 = g * 16 + nw * 2;
                unsigned b[4];
                ldsm4(b, wbhh + (unsigned)((kc * 48 + nt0) * 256));
                float* d00 = (g < 2) ? arz[0][2 * g] : ahn[0][0];
                float* d01 = (g < 2) ? arz[0][2 * g + 1] : ahn[0][1];
                float* d10 = (g < 2) ? arz[1][2 * g] : ahn[1][0];
                float* d11 = (g < 2) ? arz[1][2 * g + 1] : ahn[1][1];
                mma16(d00, a0, b[0], b[1]);
                mma16(d01, a0, b[2], b[3]);
                mma16(d10, a1, b[0], b[1]);
                mma16(d11, a1, b[2], b[3]);
            }
        }
        barg(mw);

        // epilogue(t)
#pragma unroll
        for (int jj = 0; jj < 2; jj++) {
            int col = nw * 8 + jj * 4 + lr;
            int csw = col & 3;
            int cch = col >> 2;
#pragma unroll
            for (int i = 0; i < 2; i++) {
#pragma unroll
                for (int h8 = 0; h8 < 2; h8++) {
                    int lrow = mw * 32 + i * 16 + lq + h8 * 8;
                    int ci = h8 * 2;
                    float rx = sigm(arz[i][jj][ci] + brz[jj][0]);
                    float ry = sigm(arz[i][jj][ci + 1] + brz[jj][1]);
                    float zx = sigm(arz[i][jj + 2][ci] + brz[jj][2]);
                    float zy = sigm(arz[i][jj + 2][ci + 1] + brz[jj][3]);
                    float nx = tanha(axn[i][jj][ci] + bihn[jj][0] +
                                     rx * (ahn[i][jj][ci] + bhhn[jj][0]));
                    float ny = tanha(axn[i][jj][ci + 1] + bihn[jj][1] +
                                     ry * (ahn[i][jj][ci + 1] + bhhn[jj][1]));
                    int hx = ((jj * 2 + i) * 2 + h8) * 2;
                    float hxv = nx + zx * (hf[hx] - nx);
                    float hyv = ny + zy * (hf[hx + 1] - ny);
                    hf[hx] = hxv; hf[hx + 1] = hyv;
                    hb[lrow * 64 + ((cch ^ (lrow & 7)) << 2) + csw] = packbf(hxv, hyv);
                }
            }
        }

        if (t + 1 < TT) {
            cp_wait<0>();
#pragma unroll
            for (int i = 0; i < 2; i++) {
#pragma unroll
                for (int j = 0; j < 4; j++)
#pragma unroll
                    for (int c = 0; c < 4; c++) arz[i][j][c] = 0.0f;
#pragma unroll
                for (int j = 0; j < 2; j++)
#pragma unroll
                    for (int c = 0; c < 4; c++) { axn[i][j][c] = 0.0f; ahn[i][j][c] = 0.0f; }
            }
#pragma unroll
            for (int kc = 0; kc < 8; kc++) {
                unsigned sw = (unsigned)(((kc * 2 + cm) ^ rs) << 4);
                unsigned a0[4], a1[4];
                ldsm4(a0, xs0 + sw);
                ldsm4(a1, xs1 + sw);
#pragma unroll
                for (int g = 0; g < 3; g++) {
                    int nt0 = g * 16 + nw * 2;
                    unsigned b[4];
                    ldsm4(b, wbih + (unsigned)((kc * 48 + nt0) * 256));
                    float* d00 = (g < 2) ? arz[0][2 * g] : axn[0][0];
                    float* d01 = (g < 2) ? arz[0][2 * g + 1] : axn[0][1];
                    float* d10 = (g < 2) ? arz[1][2 * g] : axn[1][0];
                    float* d11 = (g < 2) ? arz[1][2 * g + 1] : axn[1][1];
                    mma16(d00, a0, b[0], b[1]);
                    mma16(d01, a0, b[2], b[3]);
                    mma16(d10, a1, b[0], b[1]);
                    mma16(d11, a1, b[2], b[3]);
                }
            }
        }
        barg(mw);
    }

    uint32_t* hsu = reinterpret_cast<uint32_t*>(hstate);
#pragma unroll
    for (int p = 0; p < 8; p++) {
        int idx = gtid + 256 * p;
        int row = mw * 32 + (idx >> 6), c = idx & 63;
        hsu[(size_t)(m0 + row) * 64 + c] = hb[row * 64 + (((c >> 2) ^ (row & 7)) << 2) + (c & 3)];
    }
}

// ---------------- fused decoder scan: step-0 x-mma(hstate@Wih), steps>=1 h-mma ------
__global__ __launch_bounds__(512, 1) void dec_scan(const uint32_t* __restrict__ Wihg,
                                                   const uint32_t* __restrict__ Whhg,
                                                   const __nv_bfloat16* __restrict__ hstate,
                                                   const float* __restrict__ bih,
                                                   const float* __restrict__ bhh,
                                                   uint32_t* __restrict__ hallb) {
    extern __shared__ uint32_t smu[];
    uint32_t* Wih = smu;            // 24576
    uint32_t* Whh = smu + 24576;    // 24576
    uint32_t* hb = smu + 49152;     // 4096
    int tid = threadIdx.x;
    int lane = tid & 31, w = tid >> 5;
    int mw = w >> 3, nw = w & 7;
    int lq = lane >> 2, lr = lane & 3;
    int mat = lane >> 3, r8 = lane & 7;
    int m0 = blockIdx.x * 64;
    int gtid = tid & 255;

    for (int idx = tid; idx < 24576 / 4; idx += 512) {
        reinterpret_cast<uint4*>(Wih)[idx] = reinterpret_cast<const uint4*>(Wihg)[idx];
        reinterpret_cast<uint4*>(Whh)[idx] = reinterpret_cast<const uint4*>(Whhg)[idx];
    }

    float brz[2][4], bihn[2][2], bhhn[2][2];
#pragma unroll
    for (int jj = 0; jj < 2; jj++) {
        int u = nw * 16 + jj * 8 + lr * 2;
        brz[jj][0] = bih[u] + bhh[u];
        brz[jj][1] = bih[u + 1] + bhh[u + 1];
        brz[jj][2] = bih[u + 128] + bhh[u + 128];
        brz[jj][3] = bih[u + 129] + bhh[u + 129];
        bihn[jj][0] = bih[u + 256]; bihn[jj][1] = bih[u + 257];
        bhhn[jj][0] = bhh[u + 256]; bhhn[jj][1] = bhh[u + 257];
    }

    int row0 = mw * 32 + (mat & 1) * 8 + r8;
    int row1 = row0 + 16;
    int rs = row0 & 7;
    int cm = mat >> 1;
    unsigned hbb0 = s2u(hb) + row0 * 256, hbb1 = s2u(hb) + row1 * 256;
    unsigned wbih = s2u(Wih) + bpl(lane);
    unsigned wbhh = s2u(Whh) + bpl(lane);

    {
        int pfrow = mw * 32 + (gtid >> 3);
        int pfc = (gtid & 7) * 2;
        int prs = pfrow & 7;
        const uint32_t* gsrc = reinterpret_cast<const uint32_t*>(hstate) + ((size_t)m0 + pfrow) * 64;
        cpa16(hb + pfrow * 64 + ((pfc ^ prs) << 2), gsrc + pfc * 4);
        cpa16(hb + pfrow * 64 + (((pfc + 1) ^ prs) << 2), gsrc + (pfc + 1) * 4);
        cp_commit();
        cp_wait<0>();
    }

    float hf[16];
#pragma unroll
    for (int i = 0; i < 16; i++) hf[i] = 0.0f;
    __syncthreads();

    for (int s = 0; s < NSTEPS; s++) {
        float arz[2][4][4], an[2][2][4];
#pragma unroll
        for (int i = 0; i < 2; i++) {
#pragma unroll
            for (int j = 0; j < 4; j++)
#pragma unroll
                for (int c = 0; c < 4; c++) arz[i][j][c] = 0.0f;
#pragma unroll
            for (int j = 0; j < 2; j++)
#pragma unroll
                for (int c = 0; c < 4; c++) an[i][j][c] = 0.0f;
        }
        unsigned wb = (s == 0) ? wbih : wbhh;
#pragma unroll
        for (int kc = 0; kc < 8; kc++) {
            unsigned sw = (unsigned)(((kc * 2 + cm) ^ rs) << 4);
            unsigned a0[4], a1[4];
            ldsm4(a0, hbb0 + sw);
            ldsm4(a1, hbb1 + sw);
#pragma unroll
            for (int g = 0; g < 3; g++) {
                int nt0 = g * 16 + nw * 2;
                unsigned b[4];
                ldsm4(b, wb + (unsigned)((kc * 48 + nt0) * 256));
                float* d00 = (g < 2) ? arz[0][2 * g] : an[0][0];
                float* d01 = (g < 2) ? arz[0][2 * g + 1] : an[0][1];
                float* d10 = (g < 2) ? arz[1][2 * g] : an[1][0];
                float* d11 = (g < 2) ? arz[1][2 * g + 1] : an[1][1];
                mma16(d00, a0, b[0], b[1]);
                mma16(d01, a0, b[2], b[3]);
                mma16(d10, a1, b[0], b[1]);
                mma16(d11, a1, b[2], b[3]);
            }
        }
        barg(mw);

#pragma unroll
        for (int jj = 0; jj < 2; jj++) {
            int col = nw * 8 + jj * 4 + lr;
            int csw = col & 3;
            int cch = col >> 2;
#pragma unroll
            for (int i = 0; i < 2; i++) {
#pragma unroll
                for (int h8 = 0; h8 < 2; h8++) {
                    int lrow = mw * 32 + i * 16 + lq + h8 * 8;
                    int ci = h8 * 2;
                    float rx = sigm(arz[i][jj][ci] + brz[jj][0]);
                    float ry = sigm(arz[i][jj][ci + 1] + brz[jj][1]);
                    float zx = sigm(arz[i][jj + 2][ci] + brz[jj][2]);
                    float zy = sigm(arz[i][jj + 2][ci + 1] + brz[jj][3]);
                    float nx, ny;
                    if (s == 0) {
                        nx = tanha(an[i][jj][ci] + bihn[jj][0] + rx * bhhn[jj][0]);
                        ny = tanha(an[i][jj][ci + 1] + bihn[jj][1] + ry * bhhn[jj][1]);
                    } else {
                        nx = tanha(bihn[jj][0] + rx * (an[i][jj][ci] + bhhn[jj][0]));
                        ny = tanha(bihn[jj][1] + ry * (an[i][jj][ci + 1] + bhhn[jj][1]));
                    }
                    int hx = ((jj * 2 + i) * 2 + h8) * 2;
                    float hxv = nx + zx * (hf[hx] - nx);
                    float hyv = ny + zy * (hf[hx + 1] - ny);
                    hf[hx] = hxv; hf[hx + 1] = hyv;
                    hb[lrow * 64 + ((cch ^ (lrow & 7)) << 2) + csw] = packbf(hxv, hyv);
                }
            }
        }
        barg(mw);

        uint32_t* dst = hallb + ((size_t)s * BB + m0) * 64;
#pragma unroll
        for (int p = 0; p < 8; p++) {
            int idx = gtid + 256 * p;
            int row = mw * 32 + (idx >> 6), c = idx & 63;
            dst[row * 64 + c] = hb[row * 64 + (((c >> 2) ^ (row & 7)) << 2) + (c & 3)];
        }
    }
}

// ---------------- batched MLP (256 threads, measured-best config) ---------------
__global__ __launch_bounds__(256, 1) void mlp_batch(
    const __nv_bfloat16* __restrict__ hall,
    const uint32_t* __restrict__ F1g, const uint32_t* __restrict__ F2g,
    const float* __restrict__ fc1b, const float* __restrict__ fc2b,
    const float* __restrict__ fc3w, const float* __restrict__ fc3b,
    float* __restrict__ inc, int ntiles) {
    extern __shared__ uint32_t smu[];
    uint32_t* F1 = smu;                  // 16384
    uint32_t* F2 = smu + 16384;          // 8192
    uint32_t* As = smu + 24576;          // 2 x 64*68
    uint32_t* A1 = smu + 33280;          // 64*132
    float* A2T = (float*)(smu + 41728);  // 65*64
    float* B1 = (float*)(smu + 45888);
    float* B2 = (float*)(smu + 46144);
    float* B3W = (float*)(smu + 46208);
    float* B3 = (float*)(smu + 46592);   // end 46598 u32 = 186392 B

    int tid = threadIdx.x;
    int lane = tid & 31, w = tid >> 5;
    int mw = w >> 2, nw = w & 3, lq = lane >> 2, lr = lane & 3;
    int mat = lane >> 3, r8 = lane & 7;

    for (int i = tid; i < 16384; i += 256) F1[i] = F1g[i];
    for (int i = tid; i < 8192; i += 256) F2[i] = F2g[i];
    if (tid < 256) B1[tid] = fc1b[tid];
    if (tid < 64) B2[tid] = fc2b[tid];
    if (tid < 6) B3[tid] = fc3b[tid];
    for (int i = tid; i < 384; i += 256) B3W[i] = fc3w[i];

    unsigned asb = s2u(As + (mw * 32 + (mat & 1) * 8 + r8) * 68 + (mat >> 1) * 4);
    unsigned a1b0 = s2u(A1 + (mw * 32 + (mat & 1) * 8 + r8) * 132 + (mat >> 1) * 4);
    unsigned a1b1 = a1b0 + 16 * 132 * 4;
    unsigned f1b = s2u(F1) + bpl(lane);
    unsigned f2b = s2u(F2) + bpl(lane);

    int grid = gridDim.x;
    int tile0 = blockIdx.x;
    if (tile0 < ntiles) {
#pragma unroll
        for (int j = 0; j < 4; j++) {
            int idx = tid + 256 * j, row = idx >> 4, c = idx & 15;
            cpa16(As + row * 68 + c * 4, hall + ((size_t)tile0 * 64 + row) * HD + c * 8);
        }
        cp_commit();
    }
    __syncthreads();

    int it = 0;
    for (int tile = tile0; tile < ntiles; tile += grid, it++) {
        int nxt = tile + grid;
        if (nxt < ntiles) {
            uint32_t* xb = As + ((it + 1) & 1) * 4352;
#pragma unroll
            for (int j = 0; j < 4; j++) {
                int idx = tid + 256 * j, row = idx >> 4, c = idx & 15;
                cpa16(xb + row * 68 + c * 4, hall + ((size_t)nxt * 64 + row) * HD + c * 8);
            }
            cp_commit();
            cp_wait<1>();
        } else {
            cp_wait<0>();
        }
        __syncthreads();

        unsigned ab0 = asb + (unsigned)((it & 1) * 4352 * 4);
        unsigned ab1 = ab0 + 16 * 68 * 4;

        float acc1[2][8][4];
#pragma unroll
        for (int i = 0; i < 2; i++)
#pragma unroll
            for (int j = 0; j < 8; j++)
#pragma unroll
                for (int c = 0; c < 4; c++) acc1[i][j][c] = 0.0f;
#pragma unroll
        for (int kc = 0; kc < 8; kc++) {
            unsigned a0[4], a1r[4];
            ldsm4(a0, ab0 + kc * 32);
            ldsm4(a1r, ab1 + kc * 32);
#pragma unroll
            for (int p = 0; p < 4; p++) {
                int nt0 = nw * 8 + 2 * p;
                unsigned b[4];
                ldsm4(b, f1b + (unsigned)((kc * 32 + nt0) * 256));
                mma16(acc1[0][2 * p], a0, b[0], b[1]);
                mma16(acc1[0][2 * p + 1], a0, b[2], b[3]);
                mma16(acc1[1][2 * p], a1r, b[0], b[1]);
                mma16(acc1[1][2 * p + 1], a1r, b[2], b[3]);
            }
        }
#pragma unroll
        for (int j2 = 0; j2 < 8; j2++) {
            int col = nw * 64 + j2 * 8 + lr * 2;
            float2 bb = ld2(B1 + col);
#pragma unroll
            for (int i = 0; i < 2; i++) {
                int row = mw * 32 + i * 16 + lq;
                A1[row * 132 + (col >> 1)] =
                    packbf(fmaxf(acc1[i][j2][0] + bb.x, 0.0f), fmaxf(acc1[i][j2][1] + bb.y, 0.0f));
                A1[(row + 8) * 132 + (col >> 1)] =
                    packbf(fmaxf(acc1[i][j2][2] + bb.x, 0.0f), fmaxf(acc1[i][j2][3] + bb.y, 0.0f));
            }
        }
        __syncthreads();

        float acc2[2][2][4];
#pragma unroll
        for (int i = 0; i < 2; i++)
#pragma unroll
            for (int j = 0; j < 2; j++)
#pragma unroll
                for (int c = 0; c < 4; c++) acc2[i][j][c] = 0.0f;
#pragma unroll
        for (int kc = 0; kc < 16; kc++) {
            unsigned a0[4], a1r[4];
            ldsm4(a0, a1b0 + kc * 32);
            ldsm4(a1r, a1b1 + kc * 32);
            unsigned b[4];
            ldsm4(b, f2b + (unsigned)((kc * 8 + nw * 2) * 256));
            mma16(acc2[0][0], a0, b[0], b[1]);
            mma16(acc2[0][1], a0, b[2], b[3]);
            mma16(acc2[1][0], a1r, b[0], b[1]);
            mma16(acc2[1][1], a1r, b[2], b[3]);
        }
#pragma unroll
        for (int j2 = 0; j2 < 2; j2++) {
            int col = nw * 16 + j2 * 8 + lr * 2;
            float2 bb = ld2(B2 + col);
#pragma unroll
            for (int i = 0; i < 2; i++) {
                int row = mw * 32 + i * 16 + lq;
                A2T[col * 65 + row] = acc2[i][j2][0] + bb.x;
                A2T[(col + 1) * 65 + row] = acc2[i][j2][1] + bb.y;
                A2T[col * 65 + row + 8] = acc2[i][j2][2] + bb.x;
                A2T[(col + 1) * 65 + row + 8] = acc2[i][j2][3] + bb.y;
            }
        }
        __syncthreads();

#pragma unroll
        for (int p = 0; p < 2; p++) {
            int li = tid + 256 * p;
            if (li < 384) {
                int r = li & 63, c = li >> 6;
                float acc = B3[c];
#pragma unroll
                for (int k = 0; k < 64; k++) acc = fmaf(A2T[k * 65 + r], B3W[c * 64 + k], acc);
                inc[(size_t)(tile * 64 + r) * 6 + c] = acc;
            }
        }
        __syncthreads();
    }
}

// present prefix-accumulation + final output (same fp32 order as the old scan)
__global__ void prefix_kernel(const float* __restrict__ inc,
                              const float* __restrict__ present0,
                              float* __restrict__ outp) {
    int i = blockIdx.x * 256 + threadIdx.x;
    if (i < BB * 6) {
        int b = i / 6, c = i % 6;
        float pres = present0[i];
#pragma unroll
        for (int s = 0; s < NSTEPS; s++) {
            pres += inc[((size_t)s * BB + b) * 6 + c];
            outp[(size_t)b * 180 + c * 30 + s] = pres;
        }
    }
}

// ---------------- host ----------------
extern "C" void kernel_launch(void* const* d_in, const int* in_sizes, int n_in,
                              void* d_out, int out_size) {
    const float* past = (const float*)d_in[0];
    const float* conv_w = (const float*)d_in[1];
    const float* conv_b = (const float*)d_in[2];
    const float* bn_gamma = (const float*)d_in[3];
    const float* bn_beta = (const float*)d_in[4];
    const float* bn_mean = (const float*)d_in[5];
    const float* bn_var = (const float*)d_in[6];
    const float* enc_wih = (const float*)d_in[7];
    const float* enc_whh = (const float*)d_in[8];
    const float* enc_bih = (const float*)d_in[9];
    const float* enc_bhh = (const float*)d_in[10];
    const float* dec_wih = (const float*)d_in[11];
    const float* dec_whh = (const float*)d_in[12];
    const float* dec_bih = (const float*)d_in[13];
    const float* dec_bhh = (const float*)d_in[14];
    const float* fc1_w = (const float*)d_in[15];
    const float* fc1_b = (const float*)d_in[16];
    const float* fc2_w = (const float*)d_in[17];
    const float* fc2_b = (const float*)d_in[18];
    const float* fc3_w = (const float*)d_in[19];
    const float* fc3_b = (const float*)d_in[20];
    float* outp = (float*)d_out;

    __nv_bfloat16 *p_XSb, *p_hstateb;
    uint32_t *p_hallb, *p_wencih, *p_wenchh, *p_wdecih, *p_wdechh, *p_fc1tb, *p_fc2tb, *p_wconv;
    float* p_present;
    cudaGetSymbolAddress((void**)&p_XSb, g_XSb);
    cudaGetSymbolAddress((void**)&p_hstateb, g_hstateb);
    cudaGetSymbolAddress((void**)&p_hallb, g_hallb);
    cudaGetSymbolAddress((void**)&p_present, g_present);
    cudaGetSymbolAddress((void**)&p_wencih, g_wencih);
    cudaGetSymbolAddress((void**)&p_wenchh, g_wenchh);
    cudaGetSymbolAddress((void**)&p_wdecih, g_wdecih);
    cudaGetSymbolAddress((void**)&p_wdechh, g_wdechh);
    cudaGetSymbolAddress((void**)&p_fc1tb, g_fc1tb);
    cudaGetSymbolAddress((void**)&p_fc2tb, g_fc2tb);
    cudaGetSymbolAddress((void**)&p_wconv, g_wconv);
    float* p_inc = (float*)p_XSb;  // XS dead after enc_scan; reuse as inc scratch

    const int SMEM_ENC = 57344 * 4;   // 229376 B
    const int SMEM_DEC = 53248 * 4;   // 212992 B
    const int SMEM_MLPB = 46598 * 4;  // 186392 B
    cudaFuncSetAttribute(enc_scan, cudaFuncAttributeMaxDynamicSharedMemorySize, SMEM_ENC);
    cudaFuncSetAttribute(dec_scan, cudaFuncAttributeMaxDynamicSharedMemorySize, SMEM_DEC);
    cudaFuncSetAttribute(mlp_batch, cudaFuncAttributeMaxDynamicSharedMemorySize, SMEM_MLPB);

    prep_all<<<488, 256>>>(enc_wih, enc_whh, dec_wih, dec_whh, fc1_w, fc2_w, conv_w);      // 0
    conv_mma_kernel<<<BB, 256>>>(past, p_wconv, conv_b, bn_gamma, bn_beta, bn_mean,
                                 bn_var, p_present);                                       // 1
    enc_scan<<<BB / 64, 512, SMEM_ENC>>>(p_wencih, p_wenchh, p_XSb, enc_bih, enc_bhh, p_hstateb);    // 2
    dec_scan<<<BB / 64, 512, SMEM_DEC>>>(p_wdecih, p_wdechh, p_hstateb, dec_bih, dec_bhh, p_hallb);  // 3 (profiled)
    mlp_batch<<<148, 256, SMEM_MLPB>>>((const __nv_bfloat16*)p_hallb, p_fc1tb, p_fc2tb,
                                       fc1_b, fc2_b, fc3_w, fc3_b, p_inc, NSTEPS * BB / 64);         // 4
    prefix_kernel<<<(BB * 6 + 255) / 256, 256>>>(p_inc, p_present, outp);                            // 5
}